// round 12
// baseline (speedup 1.0000x reference)
#include <cuda_runtime.h>
#include <cuda_fp16.h>
#include <math.h>
#include <stdint.h>

#define Bsz  16384
#define EDIM 128
#define HIST 50
#define KC   1920   // compact K for MLP1 (zero columns of c removed)
#define ITEMV 91718
#define EPSF 1e-5f

// ---------------- scratch (device globals; no allocation allowed) ----------
__device__ float g_mm_pre[Bsz * EDIM];                       //  8.4 MB
__device__ __half g_xw[Bsz * 4 * EDIM];                      // 16.8 MB (fields 2..5 @ bi_W)
__device__ __half g_xd_hi[Bsz * EDIM];                       //  4.2 MB (x_d128 split)
__device__ __half g_xd_lo[Bsz * EDIM];
__device__ __half g_c[(size_t)Bsz * KC];                     // 63 MB (single fp16)
__device__ __half g_h1[Bsz * 512];                           // 16.8 MB
__device__ float g_part[Bsz * 4];                            // 256 KB logit partials
__device__ __half g_item16[(size_t)ITEMV * EDIM];            // 23.5 MB fp16 embedding table
__device__ __half g_W1T[512 * KC];                           //  2 MB (N-major [512][1920])
__device__ __half g_W2T[256 * 512];
__device__ __half g_mmWT[128 * 128];
__device__ __half g_biWT[128 * 128];
__device__ float g_bn1_s[512], g_bn1_t[512];
__device__ float g_bn2_s[256], g_bn2_t[256];

// ---------------- side stream for prep overlap (created at load time) ------
struct SideStream {
    cudaStream_t s;
    cudaEvent_t  fork, join, join2, join3;
    SideStream() {
        cudaStreamCreateWithFlags(&s, cudaStreamNonBlocking);
        cudaEventCreateWithFlags(&fork,  cudaEventDisableTiming);
        cudaEventCreateWithFlags(&join,  cudaEventDisableTiming);
        cudaEventCreateWithFlags(&join2, cudaEventDisableTiming);
        cudaEventCreateWithFlags(&join3, cudaEventDisableTiming);
    }
};
static SideStream g_ss;

// ================= PTX helpers (non-arch-specific only) =====================
__device__ __forceinline__ uint32_t smem_u32(const void* p) {
    uint32_t a;
    asm("{ .reg .u64 t; cvta.to.shared.u64 t, %1; cvt.u32.u64 %0, t; }"
        : "=r"(a) : "l"(p));
    return a;
}
__device__ __forceinline__ void cp_async16(uint32_t dst, const void* src) {
    asm volatile("cp.async.cg.shared.global [%0], [%1], 16;" :: "r"(dst), "l"(src));
}
#define CP_COMMIT() asm volatile("cp.async.commit_group;" ::: "memory")
#define CP_WAIT0()  asm volatile("cp.async.wait_group 0;" ::: "memory")
#define CP_WAIT1()  asm volatile("cp.async.wait_group 1;" ::: "memory")

__device__ __forceinline__ void ldsm_x4(uint32_t* r, uint32_t addr) {
    asm volatile("ldmatrix.sync.aligned.m8n8.x4.shared.b16 {%0,%1,%2,%3}, [%4];"
                 : "=r"(r[0]), "=r"(r[1]), "=r"(r[2]), "=r"(r[3]) : "r"(addr));
}
#define MMA_F16(c, a, b0v, b1v) \
    asm volatile("mma.sync.aligned.m16n8k16.row.col.f32.f16.f16.f32 " \
        "{%0,%1,%2,%3}, {%4,%5,%6,%7}, {%8,%9}, {%0,%1,%2,%3};" \
        : "+f"((c)[0]), "+f"((c)[1]), "+f"((c)[2]), "+f"((c)[3]) \
        : "r"((a)[0]), "r"((a)[1]), "r"((a)[2]), "r"((a)[3]), "r"(b0v), "r"(b1v))

// XOR-swizzled smem addressing: 128 rows x 64 B (32 fp16). unit = 16B column.
__device__ __forceinline__ uint32_t swz(int row, int unit) {
    return (uint32_t)(row * 64 + ((unit ^ ((row >> 1) & 3)) << 4));
}

__device__ __forceinline__ void split2h(float v, __half& h, __half& l) {
    h = __float2half_rn(v);
    l = __float2half_rn(v - __half2float(h));
}

// ---------------- prep kernels ----------------------------------------------
__global__ void prep_bn_kernel(const float* __restrict__ b1, const float* __restrict__ g1,
                               const float* __restrict__ be1, const float* __restrict__ rm1,
                               const float* __restrict__ rv1,
                               const float* __restrict__ b2, const float* __restrict__ g2,
                               const float* __restrict__ be2, const float* __restrict__ rm2,
                               const float* __restrict__ rv2) {
    int i = blockIdx.x * blockDim.x + threadIdx.x;
    if (i < 512) {
        float s = g1[i] * rsqrtf(rv1[i] + EPSF);
        g_bn1_s[i] = s;
        g_bn1_t[i] = (b1[i] - rm1[i]) * s + be1[i];
    }
    if (i < 256) {
        float s = g2[i] * rsqrtf(rv2[i] + EPSF);
        g_bn2_s[i] = s;
        g_bn2_t[i] = (b2[i] - rm2[i]) * s + be2[i];
    }
}

__global__ void prep_item16_kernel(const float* __restrict__ emb) {
    size_t idx = (size_t)blockIdx.x * blockDim.x + threadIdx.x;
    if (idx >= (size_t)ITEMV * EDIM) return;
    g_item16[idx] = __float2half_rn(emb[idx]);
}

__global__ void prep_w1_kernel(const float* __restrict__ W1) {
    int idx = blockIdx.x * blockDim.x + threadIdx.x;
    if (idx >= 512 * KC) return;
    int n = idx / KC;
    int k = idx % KC;
    int orig = (k < 640) ? (k + 128) : (k + 768);
    g_W1T[idx] = __float2half_rn(W1[(size_t)orig * 512 + n]);
}

__global__ void prep_w2_kernel(const float* __restrict__ W2) {
    int idx = blockIdx.x * blockDim.x + threadIdx.x;
    if (idx >= 256 * 512) return;
    int n = idx / 512;
    int k = idx % 512;
    g_W2T[idx] = __float2half_rn(W2[(size_t)k * 256 + n]);
}

__global__ void prep_sq_kernel(const float* __restrict__ W, __half* __restrict__ T) {
    int idx = blockIdx.x * blockDim.x + threadIdx.x;
    if (idx >= 128 * 128) return;
    int n = idx >> 7;
    int k = idx & 127;
    T[idx] = __float2half_rn(W[k * 128 + n]);
}

__global__ void split_xd_kernel(const float* __restrict__ x) {
    int idx = blockIdx.x * blockDim.x + threadIdx.x;
    if (idx >= Bsz * EDIM) return;
    __half h, l;
    split2h(x[idx], h, l);
    g_xd_hi[idx] = h;
    g_xd_lo[idx] = l;
}

// ======== mma.sync fp16 GEMM: C = epi(A@B^T) ================================
// CTA tile 128x128, 8 warps (4m x 2n), BK=32, 3-stage cp.async, 2 CTAs/SM,
// XOR-swizzled smem, pass-outer MMA ordering, ONE __syncthreads per K-chunk.
// A_SPLIT: A carried as fp16 hi+lo (2 data passes); else single fp16.
// MODE: 1 = fp32 + shift (mm);
//       3 = fp16 out + scale/shift + relu (h1);
//       5 = scale/shift + relu + fused W3 dot -> per-CTA partials (h2+final);
//       6 = plain fp16 out (xw)
// A_FROM_C: A rows are xs fields 2..5 stored inside c (row r -> c[r>>2, ((r&3)+1)*128 ...])
#define MMG_ARR 8192                          // 128 rows x 64 B per operand tile

template <int MODE, bool A_FROM_C, bool A_SPLIT>
__global__ void __launch_bounds__(256, 2)
mma_gemm(const __half* __restrict__ Ah, const __half* __restrict__ Al,
         const __half* __restrict__ Bh,
         int K,
         const float* __restrict__ scale, const float* __restrict__ shift,
         float* __restrict__ Cf, __half* __restrict__ Ch, int ldC,
         const float* __restrict__ w3) {
    constexpr int NA    = A_SPLIT ? 2 : 1;
    constexpr int NARR  = NA + 1;
    constexpr int STAGE = NARR * MMG_ARR;
    extern __shared__ char smem[];
    const uint32_t sbase = smem_u32(smem);
    const int tid    = threadIdx.x;
    const int wid    = tid >> 5;
    const int lane   = tid & 31;
    const int warp_m = wid & 3;
    const int warp_n = wid >> 2;
    const int m0     = blockIdx.y * 128;
    const int bcol   = blockIdx.x * 128;
    const int nch    = K >> 5;               // BK = 32

    float acc[2][8][4];
    #pragma unroll
    for (int a = 0; a < 2; a++)
        #pragma unroll
        for (int b = 0; b < 8; b++)
            #pragma unroll
            for (int c = 0; c < 4; c++) acc[a][b][c] = 0.0f;

    auto load_stage = [&](int st, int k0) {
        const uint32_t sdst = sbase + st * STAGE;
        #pragma unroll
        for (int i = 0; i < NARR * 2; i++) {
            int c   = tid + i * 256;
            int a   = c >> 9;                // operand array (uniform per i)
            int idx = c & 511;
            int r   = idx >> 2;
            int cc  = idx & 3;
            const __half* base;
            if (a == 0)                 base = Ah;
            else if (A_SPLIT && a == 1) base = Al;
            else                        base = Bh;
            const __half* g;
            if (a < NA) {
                if (A_FROM_C) {
                    int rr = m0 + r;         // global row = b*4 + jf
                    g = base + (size_t)(rr >> 2) * KC + ((rr & 3) + 1) * 128 + k0 + cc * 8;
                } else {
                    g = base + (size_t)(m0 + r) * K + k0 + cc * 8;
                }
            } else {
                g = base + (size_t)(bcol + r) * K + k0 + cc * 8;
            }
            cp_async16(sdst + a * MMG_ARR + swz(r, cc), g);
        }
        CP_COMMIT();
    };

    load_stage(0, 0);
    if (nch > 1) load_stage(1, 32);

    const int lrow = lane & 15;
    const int lcol = lane >> 4;
    int st = 0;

    for (int ch = 0; ch < nch; ch++) {
        if (ch + 1 < nch) { CP_WAIT1(); } else { CP_WAIT0(); }
        __syncthreads();
        if (ch + 2 < nch) {
            int st2 = st + 2; if (st2 >= 3) st2 -= 3;
            load_stage(st2, (ch + 2) << 5);
        }

        const uint32_t sa_hi = sbase + st * STAGE;
        const uint32_t sa_lo = sa_hi + MMG_ARR;              // valid if A_SPLIT
        const uint32_t sb_hi = sa_hi + NA * MMG_ARR;

        #pragma unroll
        for (int kk = 0; kk < 2; kk++) {
            uint32_t ah[2][4], al[2][4];
            #pragma unroll
            for (int mt = 0; mt < 2; mt++) {
                int row = warp_m * 32 + mt * 16 + lrow;
                uint32_t off = swz(row, kk * 2 + lcol);
                ldsm_x4(ah[mt], sa_hi + off);
                if (A_SPLIT) ldsm_x4(al[mt], sa_lo + off);
            }
            #pragma unroll
            for (int q = 0; q < 4; q++) {
                uint32_t bh[4];
                int row = warp_n * 64 + q * 16 + lrow;
                uint32_t off = swz(row, kk * 2 + lcol);
                ldsm_x4(bh, sb_hi + off);
                // pass-outer: acc reuse distance = 4 independent MMAs
                #pragma unroll
                for (int mt = 0; mt < 2; mt++)
                    #pragma unroll
                    for (int sl = 0; sl < 2; sl++)
                        MMA_F16(acc[mt][q * 2 + sl], ah[mt], bh[sl], bh[sl + 2]); // Ahi*B
                if (A_SPLIT) {
                    #pragma unroll
                    for (int mt = 0; mt < 2; mt++)
                        #pragma unroll
                        for (int sl = 0; sl < 2; sl++)
                            MMA_F16(acc[mt][q * 2 + sl], al[mt], bh[sl], bh[sl + 2]); // Alo*B
                }
            }
        }
        st++; if (st >= 3) st = 0;
    }

    // ---- fused epilogue ----
    float part[2][2] = {{0.f, 0.f}, {0.f, 0.f}};
    #pragma unroll
    for (int mt = 0; mt < 2; mt++) {
        const int rbase = m0 + warp_m * 32 + mt * 16 + (lane >> 2);
        #pragma unroll
        for (int nt = 0; nt < 8; nt++) {
            const int col = bcol + warp_n * 64 + nt * 8 + (lane & 3) * 2;
            float s0 = 1.0f, s1 = 1.0f, t0 = 0.0f, t1 = 0.0f;
            if (MODE == 3 || MODE == 5) { s0 = scale[col]; s1 = scale[col + 1]; }
            if (MODE == 1 || MODE == 3 || MODE == 5) { t0 = shift[col]; t1 = shift[col + 1]; }
            #pragma unroll
            for (int h = 0; h < 2; h++) {
                const size_t row = (size_t)(rbase + h * 8);
                float v0 = acc[mt][nt][h * 2 + 0];
                float v1 = acc[mt][nt][h * 2 + 1];
                if (MODE == 3 || MODE == 5) {
                    v0 = fmaxf(v0 * s0 + t0, 0.0f);
                    v1 = fmaxf(v1 * s1 + t1, 0.0f);
                } else if (MODE == 1) {
                    v0 += t0; v1 += t1;
                }
                if (MODE == 3 || MODE == 6) {
                    *(__half2*)&Ch[row * ldC + col] =
                        __halves2half2(__float2half_rn(v0), __float2half_rn(v1));
                } else if (MODE == 5) {
                    part[mt][h] += v0 * w3[col] + v1 * w3[col + 1];
                } else {
                    float2 fv; fv.x = v0; fv.y = v1;
                    *(float2*)&Cf[row * ldC + col] = fv;
                }
            }
        }
    }
    if (MODE == 5) {
        #pragma unroll
        for (int mt = 0; mt < 2; mt++) {
            #pragma unroll
            for (int h = 0; h < 2; h++) {
                float p = part[mt][h];
                p += __shfl_xor_sync(0xffffffffu, p, 1);
                p += __shfl_xor_sync(0xffffffffu, p, 2);
                if ((lane & 3) == 0) {
                    const int row = m0 + warp_m * 32 + mt * 16 + (lane >> 2) + h * 8;
                    Cf[(size_t)row * 4 + blockIdx.x * 2 + warp_n] = p;
                }
            }
        }
    }
}

// ---------------- per-row feature construction ------------------------------
__device__ __forceinline__ float block_sum_128(float v, float* sred) {
    int lane = threadIdx.x & 31, wid = threadIdx.x >> 5;
    #pragma unroll
    for (int o = 16; o; o >>= 1) v += __shfl_xor_sync(0xffffffffu, v, o);
    if (lane == 0) sred[wid] = v;
    __syncthreads();
    float s = sred[0] + sred[1] + sred[2] + sred[3];
    __syncthreads();
    return s;
}

__global__ void features_kernel(const int* __restrict__ item_id,
                                const int* __restrict__ likes,
                                const int* __restrict__ views,
                                const int* __restrict__ item_seq,
                                const float* __restrict__ cate_emb,
                                const float* __restrict__ ln_g,
                                const float* __restrict__ ln_b,
                                const float* __restrict__ se_W1,
                                const float* __restrict__ se_b1,
                                const float* __restrict__ se_W2,
                                const float* __restrict__ se_b2) {
    __shared__ float sred[4];
    __shared__ float sh_hist[4][EDIM];
    __shared__ int   scnt[4];
    __shared__ int   s_idx[HIST];
    const int b    = blockIdx.x;
    const int tid  = threadIdx.x;
    const int wid  = tid >> 5;
    const int lane = tid & 31;

    if (tid < HIST) s_idx[tid] = item_seq[(size_t)b * HIST + tid];
    __syncthreads();

    // history gather from fp16 table: lane loads 4 halves (8 B) per row
    {
        float4 hs = make_float4(0.f, 0.f, 0.f, 0.f);
        int c = 0;
        for (int t = wid; t < HIST; t += 4) {
            int s = s_idx[t];
            if (s != 0) {
                uint2 raw = ((const uint2*)(g_item16 + (size_t)s * EDIM))[lane];
                __half2 h0 = *(__half2*)&raw.x;
                __half2 h1 = *(__half2*)&raw.y;
                float2 a = __half22float2(h0);
                float2 d = __half22float2(h1);
                hs.x += a.x; hs.y += a.y; hs.z += d.x; hs.w += d.y;
                c++;
            }
        }
        ((float4*)sh_hist[wid])[lane] = hs;
        if (lane == 0) scnt[wid] = c;
    }
    __syncthreads();

    const int e = tid;
    float hsum = sh_hist[0][e] + sh_hist[1][e] + sh_hist[2][e] + sh_hist[3][e];
    int   cnt  = scnt[0] + scnt[1] + scnt[2] + scnt[3];
    float hist = hsum / (float)(cnt > 1 ? cnt : 1);
    __syncthreads();

    float mmv = g_mm_pre[(size_t)b * EDIM + e];
    float mu  = block_sum_128(mmv, sred) * (1.0f / 128.0f);
    float d   = mmv - mu;
    float var = block_sum_128(d * d, sred) * (1.0f / 128.0f);
    float mm  = fmaxf(d * rsqrtf(var + EPSF) * ln_g[e] + ln_b[e], 0.0f);

    int   id   = item_id[b];
    float item = (id == 0) ? 0.0f : __half2float(g_item16[(size_t)id * EDIM + e]);
    float like = cate_emb[(size_t)likes[b] * EDIM + e];
    float view = cate_emb[(size_t)views[b] * EDIM + e];

    float x[6] = {0.0f, like, view, item, mm, hist};

    float z[6];
    z[0] = 0.0f;
    #pragma unroll
    for (int f = 1; f < 6; f++) z[f] = block_sum_128(x[f], sred) * (1.0f / 128.0f);

    float w[6];
    {
        float h[3];
        #pragma unroll
        for (int j = 0; j < 3; j++) {
            float s = se_b1[j];
            #pragma unroll
            for (int f = 0; f < 6; f++) s += z[f] * se_W1[f * 3 + j];
            h[j] = fmaxf(s, 0.0f);
        }
        #pragma unroll
        for (int f = 0; f < 6; f++) {
            float s = se_b2[f];
            #pragma unroll
            for (int j = 0; j < 3; j++) s += h[j] * se_W2[j * 6 + f];
            w[f] = 1.0f / (1.0f + expf(-s));
        }
    }

    #pragma unroll
    for (int f = 1; f < 6; f++) {
        float xv = x[f] * w[f];
        g_c[(size_t)b * KC + (f - 1) * EDIM + e] = __float2half_rn(xv);
    }
}

// ---------------- bilinear pair products: all fp16 in/out -------------------
__global__ void pairs_kernel() {
    const int b = blockIdx.x;
    const int e = threadIdx.x;
    const size_t cb0 = (size_t)b * KC + e;
    float xs0 = __half2float(g_c[cb0]);
    float xs1 = __half2float(g_c[cb0 + EDIM]);
    float xs2 = __half2float(g_c[cb0 + 2 * EDIM]);
    float xs3 = __half2float(g_c[cb0 + 3 * EDIM]);
    const size_t x4 = (size_t)b * 4 * EDIM + e;
    float xw0 = __half2float(g_xw[x4]);
    float xw1 = __half2float(g_xw[x4 + EDIM]);
    float xw2 = __half2float(g_xw[x4 + 2 * EDIM]);
    float xw3 = __half2float(g_xw[x4 + 3 * EDIM]);
    float p[10] = { xs0 * xw0, xs0 * xw1, xs0 * xw2, xs0 * xw3,
                    xs1 * xw1, xs1 * xw2, xs1 * xw3,
                    xs2 * xw2, xs2 * xw3,
                    xs3 * xw3 };
    const size_t cb = cb0 + 640;
    #pragma unroll
    for (int pr = 0; pr < 10; pr++)
        g_c[cb + pr * EDIM] = __float2half_rn(p[pr]);
}

// ---------------- final: sum partials + bias + sigmoid ---------------------
__global__ void final_sig_kernel(const float* __restrict__ b3, float* __restrict__ out) {
    int b = blockIdx.x * blockDim.x + threadIdx.x;
    if (b >= Bsz) return;
    float l = g_part[b * 4] + g_part[b * 4 + 1] + g_part[b * 4 + 2] + g_part[b * 4 + 3]
            + b3[0];
    out[b] = 1.0f / (1.0f + expf(-l));
}

// ---------------- launch ----------------------------------------------------
extern "C" void kernel_launch(void* const* d_in, const int* in_sizes, int n_in,
                              void* d_out, int out_size) {
    const int*   item_id   = (const int*)  d_in[0];
    const float* x_d128    = (const float*)d_in[1];
    const int*   likes     = (const int*)  d_in[2];
    const int*   views     = (const int*)  d_in[3];
    const int*   item_seq  = (const int*)  d_in[4];
    const float* item_emb  = (const float*)d_in[5];
    const float* cate_emb  = (const float*)d_in[6];
    const float* mm_W      = (const float*)d_in[7];
    const float* mm_b      = (const float*)d_in[8];
    const float* ln_g      = (const float*)d_in[9];
    const float* ln_b      = (const float*)d_in[10];
    const float* se_W1     = (const float*)d_in[11];
    const float* se_b1     = (const float*)d_in[12];
    const float* se_W2     = (const float*)d_in[13];
    const float* se_b2     = (const float*)d_in[14];
    const float* bi_W      = (const float*)d_in[15];
    const float* mlp_W1    = (const float*)d_in[16];
    const float* mlp_b1    = (const float*)d_in[17];
    const float* bn1_g     = (const float*)d_in[18];
    const float* bn1_b     = (const float*)d_in[19];
    const float* bn1_rm    = (const float*)d_in[20];
    const float* bn1_rv    = (const float*)d_in[21];
    const float* mlp_W2    = (const float*)d_in[22];
    const float* mlp_b2    = (const float*)d_in[23];
    const float* bn2_g     = (const float*)d_in[24];
    const float* bn2_b     = (const float*)d_in[25];
    const float* bn2_rm    = (const float*)d_in[26];
    const float* bn2_rv    = (const float*)d_in[27];
    const float* mlp_W3    = (const float*)d_in[28];
    const float* mlp_b3    = (const float*)d_in[29];
    float*       out       = (float*)d_out;

    float *p_mm_pre, *p_part;
    float *p_bn1_s, *p_bn1_t, *p_bn2_s, *p_bn2_t;
    __half *p_c, *p_h1, *p_xw, *p_W1T, *p_W2T, *p_xd_hi, *p_xd_lo, *p_mmWT, *p_biWT;
    cudaGetSymbolAddress((void**)&p_mm_pre, g_mm_pre);
    cudaGetSymbolAddress((void**)&p_xw,     g_xw);
    cudaGetSymbolAddress((void**)&p_part,   g_part);
    cudaGetSymbolAddress((void**)&p_c,      g_c);
    cudaGetSymbolAddress((void**)&p_h1,     g_h1);
    cudaGetSymbolAddress((void**)&p_W1T,    g_W1T);
    cudaGetSymbolAddress((void**)&p_W2T,    g_W2T);
    cudaGetSymbolAddress((void**)&p_xd_hi,  g_xd_hi);
    cudaGetSymbolAddress((void**)&p_xd_lo,  g_xd_lo);
    cudaGetSymbolAddress((void**)&p_mmWT,   g_mmWT);
    cudaGetSymbolAddress((void**)&p_biWT,   g_biWT);
    cudaGetSymbolAddress((void**)&p_bn1_s,  g_bn1_s);
    cudaGetSymbolAddress((void**)&p_bn1_t,  g_bn1_t);
    cudaGetSymbolAddress((void**)&p_bn2_s,  g_bn2_s);
    cudaGetSymbolAddress((void**)&p_bn2_t,  g_bn2_t);

    const int SM_MM  = 3 * 3 * MMG_ARR;   // A split + B = 3 arrays
    const int SM_ONE = 2 * 3 * MMG_ARR;   // A + B = 2 arrays
    cudaFuncSetAttribute((const void*)mma_gemm<1, false, true >,
                         cudaFuncAttributeMaxDynamicSharedMemorySize, SM_MM);
    cudaFuncSetAttribute((const void*)mma_gemm<6, true,  false>,
                         cudaFuncAttributeMaxDynamicSharedMemorySize, SM_ONE);
    cudaFuncSetAttribute((const void*)mma_gemm<3, false, false>,
                         cudaFuncAttributeMaxDynamicSharedMemorySize, SM_ONE);
    cudaFuncSetAttribute((const void*)mma_gemm<5, false, false>,
                         cudaFuncAttributeMaxDynamicSharedMemorySize, SM_ONE);

    // ---- fork: preps on side stream ----
    cudaEventRecord(g_ss.fork, 0);
    cudaStreamWaitEvent(g_ss.s, g_ss.fork, 0);
    prep_sq_kernel<<<(128 * 128 + 255) / 256, 256, 0, g_ss.s>>>(mm_W, p_mmWT);
    cudaEventRecord(g_ss.join2, g_ss.s);          // mm GEMM needs mmWT
    prep_item16_kernel<<<(int)(((size_t)ITEMV * EDIM + 255) / 256), 256, 0, g_ss.s>>>(item_emb);
    cudaEventRecord(g_ss.join3, g_ss.s);          // features needs item16
    prep_bn_kernel<<<1, 512, 0, g_ss.s>>>(mlp_b1, bn1_g, bn1_b, bn1_rm, bn1_rv,
                                          mlp_b2, bn2_g, bn2_b, bn2_rm, bn2_rv);
    prep_w1_kernel<<<(512 * KC + 255) / 256, 256, 0, g_ss.s>>>(mlp_W1);
    prep_w2_kernel<<<(256 * 512 + 255) / 256, 256, 0, g_ss.s>>>(mlp_W2);
    prep_sq_kernel<<<(128 * 128 + 255) / 256, 256, 0, g_ss.s>>>(bi_W, p_biWT);
    cudaEventRecord(g_ss.join, g_ss.s);

    // ---- main chain ----
    split_xd_kernel<<<(Bsz * EDIM + 255) / 256, 256>>>(x_d128);
    cudaStreamWaitEvent(0, g_ss.join2, 0);

    // mm_pre = item_emb_d128 @ mm_W + mm_b   (A split; MODE 1)
    mma_gemm<1, false, true><<<dim3(1, Bsz / 128), 256, SM_MM>>>(
        p_xd_hi, p_xd_lo, p_mmWT, 128,
        nullptr, mm_b, p_mm_pre, nullptr, 128, nullptr);

    cudaStreamWaitEvent(0, g_ss.join3, 0);

    // per-row features -> c[:,0:640]
    features_kernel<<<Bsz, 128>>>(item_id, likes, views, item_seq,
                                  cate_emb, ln_g, ln_b,
                                  se_W1, se_b1, se_W2, se_b2);

    cudaStreamWaitEvent(0, g_ss.join, 0);

    // xw = xs(fields 2..5, from c) @ bi_W -> fp16  (MODE 6, A_FROM_C)
    mma_gemm<6, true, false><<<dim3(1, (Bsz * 4) / 128), 256, SM_ONE>>>(
        p_c, nullptr, p_biWT, 128,
        nullptr, nullptr, nullptr, p_xw, 128, nullptr);

    // pair products -> c[:, 640:1920]  (all fp16)
    pairs_kernel<<<Bsz, 128>>>();

    // h1 = relu(bn1(c @ W1c^T + b1))   (MODE 3, K=1920)
    mma_gemm<3, false, false><<<dim3(512 / 128, Bsz / 128), 256, SM_ONE>>>(
        p_c, nullptr, p_W1T, KC,
        p_bn1_s, p_bn1_t, nullptr, p_h1, 512, nullptr);

    // h2+final: relu(bn2(h1 @ W2^T + b2)) . W3 -> partials (MODE 5)
    mma_gemm<5, false, false><<<dim3(256 / 128, Bsz / 128), 256, SM_ONE>>>(
        p_h1, nullptr, p_W2T, 512,
        p_bn2_s, p_bn2_t, p_part, nullptr, 4, mlp_W3);

    // logits -> sigmoid
    final_sig_kernel<<<(Bsz + 255) / 256, 256>>>(mlp_b3, out);
}

// round 13
// speedup vs baseline: 1.0397x; 1.0397x over previous
#include <cuda_runtime.h>
#include <cuda_fp16.h>
#include <math.h>
#include <stdint.h>

#define Bsz  16384
#define EDIM 128
#define HIST 50
#define KC   1920   // compact K for MLP1 (zero columns of c removed)
#define EPSF 1e-5f

// ---------------- scratch (device globals; no allocation allowed) ----------
__device__ float g_mm_pre[Bsz * EDIM];                       //  8.4 MB
__device__ __half g_xw[Bsz * 4 * EDIM];                      // 16.8 MB (fields 2..5 @ bi_W)
__device__ __half g_xd_hi[Bsz * EDIM];                       //  4.2 MB (x_d128 split)
__device__ __half g_xd_lo[Bsz * EDIM];
__device__ __half g_c[(size_t)Bsz * KC];                     // 63 MB (single fp16)
__device__ __half g_h1[Bsz * 512];                           // 16.8 MB
__device__ float g_part[Bsz * 4];                            // 256 KB logit partials
__device__ __half g_W1T[512 * KC];                           //  2 MB (N-major [512][1920])
__device__ __half g_W2T[256 * 512];
__device__ __half g_mmWT[128 * 128];
__device__ __half g_biWT[128 * 128];
__device__ float g_bn1_s[512], g_bn1_t[512];
__device__ float g_bn2_s[256], g_bn2_t[256];

// ---------------- side stream for prep overlap (created at load time) ------
struct SideStream {
    cudaStream_t s;
    cudaEvent_t  fork, join, join2;
    SideStream() {
        cudaStreamCreateWithFlags(&s, cudaStreamNonBlocking);
        cudaEventCreateWithFlags(&fork,  cudaEventDisableTiming);
        cudaEventCreateWithFlags(&join,  cudaEventDisableTiming);
        cudaEventCreateWithFlags(&join2, cudaEventDisableTiming);
    }
};
static SideStream g_ss;

// ================= PTX helpers (non-arch-specific only) =====================
__device__ __forceinline__ uint32_t smem_u32(const void* p) {
    uint32_t a;
    asm("{ .reg .u64 t; cvta.to.shared.u64 t, %1; cvt.u32.u64 %0, t; }"
        : "=r"(a) : "l"(p));
    return a;
}
__device__ __forceinline__ void cp_async16(uint32_t dst, const void* src) {
    asm volatile("cp.async.cg.shared.global [%0], [%1], 16;" :: "r"(dst), "l"(src));
}
#define CP_COMMIT() asm volatile("cp.async.commit_group;" ::: "memory")
#define CP_WAIT0()  asm volatile("cp.async.wait_group 0;" ::: "memory")
#define CP_WAIT1()  asm volatile("cp.async.wait_group 1;" ::: "memory")

__device__ __forceinline__ void ldsm_x4(uint32_t* r, uint32_t addr) {
    asm volatile("ldmatrix.sync.aligned.m8n8.x4.shared.b16 {%0,%1,%2,%3}, [%4];"
                 : "=r"(r[0]), "=r"(r[1]), "=r"(r[2]), "=r"(r[3]) : "r"(addr));
}
#define MMA_F16(c, a, b0v, b1v) \
    asm volatile("mma.sync.aligned.m16n8k16.row.col.f32.f16.f16.f32 " \
        "{%0,%1,%2,%3}, {%4,%5,%6,%7}, {%8,%9}, {%0,%1,%2,%3};" \
        : "+f"((c)[0]), "+f"((c)[1]), "+f"((c)[2]), "+f"((c)[3]) \
        : "r"((a)[0]), "r"((a)[1]), "r"((a)[2]), "r"((a)[3]), "r"(b0v), "r"(b1v))

// XOR-swizzled smem addressing: 128 rows x 64 B (32 fp16). unit = 16B column.
__device__ __forceinline__ uint32_t swz(int row, int unit) {
    return (uint32_t)(row * 64 + ((unit ^ ((row >> 1) & 3)) << 4));
}

__device__ __forceinline__ void split2h(float v, __half& h, __half& l) {
    h = __float2half_rn(v);
    l = __float2half_rn(v - __half2float(h));
}

// ---------------- prep kernels ----------------------------------------------
__global__ void prep_bn_kernel(const float* __restrict__ b1, const float* __restrict__ g1,
                               const float* __restrict__ be1, const float* __restrict__ rm1,
                               const float* __restrict__ rv1,
                               const float* __restrict__ b2, const float* __restrict__ g2,
                               const float* __restrict__ be2, const float* __restrict__ rm2,
                               const float* __restrict__ rv2) {
    int i = blockIdx.x * blockDim.x + threadIdx.x;
    if (i < 512) {
        float s = g1[i] * rsqrtf(rv1[i] + EPSF);
        g_bn1_s[i] = s;
        g_bn1_t[i] = (b1[i] - rm1[i]) * s + be1[i];
    }
    if (i < 256) {
        float s = g2[i] * rsqrtf(rv2[i] + EPSF);
        g_bn2_s[i] = s;
        g_bn2_t[i] = (b2[i] - rm2[i]) * s + be2[i];
    }
}

__global__ void prep_w1_kernel(const float* __restrict__ W1) {
    int idx = blockIdx.x * blockDim.x + threadIdx.x;
    if (idx >= 512 * KC) return;
    int n = idx / KC;
    int k = idx % KC;
    int orig = (k < 640) ? (k + 128) : (k + 768);
    g_W1T[idx] = __float2half_rn(W1[(size_t)orig * 512 + n]);
}

__global__ void prep_w2_kernel(const float* __restrict__ W2) {
    int idx = blockIdx.x * blockDim.x + threadIdx.x;
    if (idx >= 256 * 512) return;
    int n = idx / 512;
    int k = idx % 512;
    g_W2T[idx] = __float2half_rn(W2[(size_t)k * 256 + n]);
}

__global__ void prep_sq_kernel(const float* __restrict__ W, __half* __restrict__ T) {
    int idx = blockIdx.x * blockDim.x + threadIdx.x;
    if (idx >= 128 * 128) return;
    int n = idx >> 7;
    int k = idx & 127;
    T[idx] = __float2half_rn(W[k * 128 + n]);
}

__global__ void split_xd_kernel(const float* __restrict__ x) {
    int idx = blockIdx.x * blockDim.x + threadIdx.x;
    if (idx >= Bsz * EDIM) return;
    __half h, l;
    split2h(x[idx], h, l);
    g_xd_hi[idx] = h;
    g_xd_lo[idx] = l;
}

// ======== mma.sync fp16 GEMM: C = epi(A@B^T) ================================
// CTA tile 128x128, 8 warps (4m x 2n), BK=32, 3-stage cp.async, 2 CTAs/SM,
// XOR-swizzled smem, pass-outer MMA ordering, ONE __syncthreads per K-chunk.
// A_SPLIT: A carried as fp16 hi+lo (2 data passes); else single fp16.
// MODE: 1 = fp32 + shift (mm);
//       3 = fp16 out + scale/shift + relu (h1);
//       5 = scale/shift + relu + fused W3 dot -> per-CTA partials (h2+final);
//       6 = plain fp16 out (xw)
// A_FROM_C: A rows are xs fields 2..5 stored inside c (row r -> c[r>>2, ((r&3)+1)*128 ...])
#define MMG_ARR 8192                          // 128 rows x 64 B per operand tile

template <int MODE, bool A_FROM_C, bool A_SPLIT>
__global__ void __launch_bounds__(256, 2)
mma_gemm(const __half* __restrict__ Ah, const __half* __restrict__ Al,
         const __half* __restrict__ Bh,
         int K,
         const float* __restrict__ scale, const float* __restrict__ shift,
         float* __restrict__ Cf, __half* __restrict__ Ch, int ldC,
         const float* __restrict__ w3) {
    constexpr int NA    = A_SPLIT ? 2 : 1;
    constexpr int NARR  = NA + 1;
    constexpr int STAGE = NARR * MMG_ARR;
    extern __shared__ char smem[];
    const uint32_t sbase = smem_u32(smem);
    const int tid    = threadIdx.x;
    const int wid    = tid >> 5;
    const int lane   = tid & 31;
    const int warp_m = wid & 3;
    const int warp_n = wid >> 2;
    const int m0     = blockIdx.y * 128;
    const int bcol   = blockIdx.x * 128;
    const int nch    = K >> 5;               // BK = 32

    float acc[2][8][4];
    #pragma unroll
    for (int a = 0; a < 2; a++)
        #pragma unroll
        for (int b = 0; b < 8; b++)
            #pragma unroll
            for (int c = 0; c < 4; c++) acc[a][b][c] = 0.0f;

    auto load_stage = [&](int st, int k0) {
        const uint32_t sdst = sbase + st * STAGE;
        #pragma unroll
        for (int i = 0; i < NARR * 2; i++) {
            int c   = tid + i * 256;
            int a   = c >> 9;                // operand array (uniform per i)
            int idx = c & 511;
            int r   = idx >> 2;
            int cc  = idx & 3;
            const __half* base;
            if (a == 0)                 base = Ah;
            else if (A_SPLIT && a == 1) base = Al;
            else                        base = Bh;
            const __half* g;
            if (a < NA) {
                if (A_FROM_C) {
                    int rr = m0 + r;         // global row = b*4 + jf
                    g = base + (size_t)(rr >> 2) * KC + ((rr & 3) + 1) * 128 + k0 + cc * 8;
                } else {
                    g = base + (size_t)(m0 + r) * K + k0 + cc * 8;
                }
            } else {
                g = base + (size_t)(bcol + r) * K + k0 + cc * 8;
            }
            cp_async16(sdst + a * MMG_ARR + swz(r, cc), g);
        }
        CP_COMMIT();
    };

    load_stage(0, 0);
    if (nch > 1) load_stage(1, 32);

    const int lrow = lane & 15;
    const int lcol = lane >> 4;
    int st = 0;

    for (int ch = 0; ch < nch; ch++) {
        if (ch + 1 < nch) { CP_WAIT1(); } else { CP_WAIT0(); }
        __syncthreads();
        if (ch + 2 < nch) {
            int st2 = st + 2; if (st2 >= 3) st2 -= 3;
            load_stage(st2, (ch + 2) << 5);
        }

        const uint32_t sa_hi = sbase + st * STAGE;
        const uint32_t sa_lo = sa_hi + MMG_ARR;              // valid if A_SPLIT
        const uint32_t sb_hi = sa_hi + NA * MMG_ARR;

        #pragma unroll
        for (int kk = 0; kk < 2; kk++) {
            uint32_t ah[2][4], al[2][4];
            #pragma unroll
            for (int mt = 0; mt < 2; mt++) {
                int row = warp_m * 32 + mt * 16 + lrow;
                uint32_t off = swz(row, kk * 2 + lcol);
                ldsm_x4(ah[mt], sa_hi + off);
                if (A_SPLIT) ldsm_x4(al[mt], sa_lo + off);
            }
            #pragma unroll
            for (int q = 0; q < 4; q++) {
                uint32_t bh[4];
                int row = warp_n * 64 + q * 16 + lrow;
                uint32_t off = swz(row, kk * 2 + lcol);
                ldsm_x4(bh, sb_hi + off);
                // pass-outer: acc reuse distance = 4 independent MMAs
                #pragma unroll
                for (int mt = 0; mt < 2; mt++)
                    #pragma unroll
                    for (int sl = 0; sl < 2; sl++)
                        MMA_F16(acc[mt][q * 2 + sl], ah[mt], bh[sl], bh[sl + 2]); // Ahi*B
                if (A_SPLIT) {
                    #pragma unroll
                    for (int mt = 0; mt < 2; mt++)
                        #pragma unroll
                        for (int sl = 0; sl < 2; sl++)
                            MMA_F16(acc[mt][q * 2 + sl], al[mt], bh[sl], bh[sl + 2]); // Alo*B
                }
            }
        }
        st++; if (st >= 3) st = 0;
    }

    // ---- fused epilogue ----
    float part[2][2] = {{0.f, 0.f}, {0.f, 0.f}};
    #pragma unroll
    for (int mt = 0; mt < 2; mt++) {
        const int rbase = m0 + warp_m * 32 + mt * 16 + (lane >> 2);
        #pragma unroll
        for (int nt = 0; nt < 8; nt++) {
            const int col = bcol + warp_n * 64 + nt * 8 + (lane & 3) * 2;
            float s0 = 1.0f, s1 = 1.0f, t0 = 0.0f, t1 = 0.0f;
            if (MODE == 3 || MODE == 5) { s0 = scale[col]; s1 = scale[col + 1]; }
            if (MODE == 1 || MODE == 3 || MODE == 5) { t0 = shift[col]; t1 = shift[col + 1]; }
            #pragma unroll
            for (int h = 0; h < 2; h++) {
                const size_t row = (size_t)(rbase + h * 8);
                float v0 = acc[mt][nt][h * 2 + 0];
                float v1 = acc[mt][nt][h * 2 + 1];
                if (MODE == 3 || MODE == 5) {
                    v0 = fmaxf(v0 * s0 + t0, 0.0f);
                    v1 = fmaxf(v1 * s1 + t1, 0.0f);
                } else if (MODE == 1) {
                    v0 += t0; v1 += t1;
                }
                if (MODE == 3 || MODE == 6) {
                    *(__half2*)&Ch[row * ldC + col] =
                        __halves2half2(__float2half_rn(v0), __float2half_rn(v1));
                } else if (MODE == 5) {
                    part[mt][h] += v0 * w3[col] + v1 * w3[col + 1];
                } else {
                    float2 fv; fv.x = v0; fv.y = v1;
                    *(float2*)&Cf[row * ldC + col] = fv;
                }
            }
        }
    }
    if (MODE == 5) {
        #pragma unroll
        for (int mt = 0; mt < 2; mt++) {
            #pragma unroll
            for (int h = 0; h < 2; h++) {
                float p = part[mt][h];
                p += __shfl_xor_sync(0xffffffffu, p, 1);
                p += __shfl_xor_sync(0xffffffffu, p, 2);
                if ((lane & 3) == 0) {
                    const int row = m0 + warp_m * 32 + mt * 16 + (lane >> 2) + h * 8;
                    Cf[(size_t)row * 4 + blockIdx.x * 2 + warp_n] = p;
                }
            }
        }
    }
}

// ---------------- per-row feature construction (256 threads) -----------------
// Warps 0-7 all gather history (halved latency chain); threads 0-127 do the rest.
__device__ __forceinline__ float block_sum_128(float v, float* sred) {
    int lane = threadIdx.x & 31, wid = threadIdx.x >> 5;
    #pragma unroll
    for (int o = 16; o; o >>= 1) v += __shfl_xor_sync(0xffffffffu, v, o);
    if (lane == 0) sred[wid] = v;
    __syncthreads();
    float s = sred[0] + sred[1] + sred[2] + sred[3];
    __syncthreads();
    return s;
}

__global__ void __launch_bounds__(256)
features_kernel(const int* __restrict__ item_id,
                const int* __restrict__ likes,
                const int* __restrict__ views,
                const int* __restrict__ item_seq,
                const float* __restrict__ item_emb,
                const float* __restrict__ cate_emb,
                const float* __restrict__ ln_g,
                const float* __restrict__ ln_b,
                const float* __restrict__ se_W1,
                const float* __restrict__ se_b1,
                const float* __restrict__ se_W2,
                const float* __restrict__ se_b2) {
    __shared__ float sred[4];
    __shared__ float sh_hist[8][EDIM];
    __shared__ int   scnt[8];
    __shared__ int   s_idx[HIST];
    const int b    = blockIdx.x;
    const int tid  = threadIdx.x;
    const int wid  = tid >> 5;
    const int lane = tid & 31;

    if (tid < HIST) s_idx[tid] = item_seq[(size_t)b * HIST + tid];
    __syncthreads();

    // history gather: 8 warps, warp w handles rows w, w+8, ... (max 7 iters)
    {
        float4 hs = make_float4(0.f, 0.f, 0.f, 0.f);
        int c = 0;
        for (int t = wid; t < HIST; t += 8) {
            int s = s_idx[t];
            if (s != 0) {
                float4 v = ((const float4*)(item_emb + (size_t)s * EDIM))[lane];
                hs.x += v.x; hs.y += v.y; hs.z += v.z; hs.w += v.w;
                c++;
            }
        }
        ((float4*)sh_hist[wid])[lane] = hs;
        if (lane == 0) scnt[wid] = c;
    }
    __syncthreads();

    if (tid >= 128) return;   // only first 4 warps continue
    const int e = tid;
    float hsum = 0.0f;
    int   cnt  = 0;
    #pragma unroll
    for (int w = 0; w < 8; w++) { hsum += sh_hist[w][e]; cnt += scnt[w]; }
    float hist = hsum / (float)(cnt > 1 ? cnt : 1);
    __syncthreads();

    float mmv = g_mm_pre[(size_t)b * EDIM + e];
    float mu  = block_sum_128(mmv, sred) * (1.0f / 128.0f);
    float d   = mmv - mu;
    float var = block_sum_128(d * d, sred) * (1.0f / 128.0f);
    float mm  = fmaxf(d * rsqrtf(var + EPSF) * ln_g[e] + ln_b[e], 0.0f);

    int   id   = item_id[b];
    float item = (id == 0) ? 0.0f : item_emb[(size_t)id * EDIM + e];
    float like = cate_emb[(size_t)likes[b] * EDIM + e];
    float view = cate_emb[(size_t)views[b] * EDIM + e];

    float x[6] = {0.0f, like, view, item, mm, hist};

    float z[6];
    z[0] = 0.0f;
    #pragma unroll
    for (int f = 1; f < 6; f++) z[f] = block_sum_128(x[f], sred) * (1.0f / 128.0f);

    float w[6];
    {
        float h[3];
        #pragma unroll
        for (int j = 0; j < 3; j++) {
            float s = se_b1[j];
            #pragma unroll
            for (int f = 0; f < 6; f++) s += z[f] * se_W1[f * 3 + j];
            h[j] = fmaxf(s, 0.0f);
        }
        #pragma unroll
        for (int f = 0; f < 6; f++) {
            float s = se_b2[f];
            #pragma unroll
            for (int j = 0; j < 3; j++) s += h[j] * se_W2[j * 6 + f];
            w[f] = 1.0f / (1.0f + expf(-s));
        }
    }

    #pragma unroll
    for (int f = 1; f < 6; f++) {
        float xv = x[f] * w[f];
        g_c[(size_t)b * KC + (f - 1) * EDIM + e] = __float2half_rn(xv);
    }
}

// ---------------- bilinear pair products: all fp16 in/out -------------------
__global__ void pairs_kernel() {
    const int b = blockIdx.x;
    const int e = threadIdx.x;
    const size_t cb0 = (size_t)b * KC + e;
    float xs0 = __half2float(g_c[cb0]);
    float xs1 = __half2float(g_c[cb0 + EDIM]);
    float xs2 = __half2float(g_c[cb0 + 2 * EDIM]);
    float xs3 = __half2float(g_c[cb0 + 3 * EDIM]);
    const size_t x4 = (size_t)b * 4 * EDIM + e;
    float xw0 = __half2float(g_xw[x4]);
    float xw1 = __half2float(g_xw[x4 + EDIM]);
    float xw2 = __half2float(g_xw[x4 + 2 * EDIM]);
    float xw3 = __half2float(g_xw[x4 + 3 * EDIM]);
    float p[10] = { xs0 * xw0, xs0 * xw1, xs0 * xw2, xs0 * xw3,
                    xs1 * xw1, xs1 * xw2, xs1 * xw3,
                    xs2 * xw2, xs2 * xw3,
                    xs3 * xw3 };
    const size_t cb = cb0 + 640;
    #pragma unroll
    for (int pr = 0; pr < 10; pr++)
        g_c[cb + pr * EDIM] = __float2half_rn(p[pr]);
}

// ---------------- final: sum partials + bias + sigmoid ---------------------
__global__ void final_sig_kernel(const float* __restrict__ b3, float* __restrict__ out) {
    int b = blockIdx.x * blockDim.x + threadIdx.x;
    if (b >= Bsz) return;
    float l = g_part[b * 4] + g_part[b * 4 + 1] + g_part[b * 4 + 2] + g_part[b * 4 + 3]
            + b3[0];
    out[b] = 1.0f / (1.0f + expf(-l));
}

// ---------------- launch ----------------------------------------------------
extern "C" void kernel_launch(void* const* d_in, const int* in_sizes, int n_in,
                              void* d_out, int out_size) {
    const int*   item_id   = (const int*)  d_in[0];
    const float* x_d128    = (const float*)d_in[1];
    const int*   likes     = (const int*)  d_in[2];
    const int*   views     = (const int*)  d_in[3];
    const int*   item_seq  = (const int*)  d_in[4];
    const float* item_emb  = (const float*)d_in[5];
    const float* cate_emb  = (const float*)d_in[6];
    const float* mm_W      = (const float*)d_in[7];
    const float* mm_b      = (const float*)d_in[8];
    const float* ln_g      = (const float*)d_in[9];
    const float* ln_b      = (const float*)d_in[10];
    const float* se_W1     = (const float*)d_in[11];
    const float* se_b1     = (const float*)d_in[12];
    const float* se_W2     = (const float*)d_in[13];
    const float* se_b2     = (const float*)d_in[14];
    const float* bi_W      = (const float*)d_in[15];
    const float* mlp_W1    = (const float*)d_in[16];
    const float* mlp_b1    = (const float*)d_in[17];
    const float* bn1_g     = (const float*)d_in[18];
    const float* bn1_b     = (const float*)d_in[19];
    const float* bn1_rm    = (const float*)d_in[20];
    const float* bn1_rv    = (const float*)d_in[21];
    const float* mlp_W2    = (const float*)d_in[22];
    const float* mlp_b2    = (const float*)d_in[23];
    const float* bn2_g     = (const float*)d_in[24];
    const float* bn2_b     = (const float*)d_in[25];
    const float* bn2_rm    = (const float*)d_in[26];
    const float* bn2_rv    = (const float*)d_in[27];
    const float* mlp_W3    = (const float*)d_in[28];
    const float* mlp_b3    = (const float*)d_in[29];
    float*       out       = (float*)d_out;

    float *p_mm_pre, *p_part;
    float *p_bn1_s, *p_bn1_t, *p_bn2_s, *p_bn2_t;
    __half *p_c, *p_h1, *p_xw, *p_W1T, *p_W2T, *p_xd_hi, *p_xd_lo, *p_mmWT, *p_biWT;
    cudaGetSymbolAddress((void**)&p_mm_pre, g_mm_pre);
    cudaGetSymbolAddress((void**)&p_xw,     g_xw);
    cudaGetSymbolAddress((void**)&p_part,   g_part);
    cudaGetSymbolAddress((void**)&p_c,      g_c);
    cudaGetSymbolAddress((void**)&p_h1,     g_h1);
    cudaGetSymbolAddress((void**)&p_W1T,    g_W1T);
    cudaGetSymbolAddress((void**)&p_W2T,    g_W2T);
    cudaGetSymbolAddress((void**)&p_xd_hi,  g_xd_hi);
    cudaGetSymbolAddress((void**)&p_xd_lo,  g_xd_lo);
    cudaGetSymbolAddress((void**)&p_mmWT,   g_mmWT);
    cudaGetSymbolAddress((void**)&p_biWT,   g_biWT);
    cudaGetSymbolAddress((void**)&p_bn1_s,  g_bn1_s);
    cudaGetSymbolAddress((void**)&p_bn1_t,  g_bn1_t);
    cudaGetSymbolAddress((void**)&p_bn2_s,  g_bn2_s);
    cudaGetSymbolAddress((void**)&p_bn2_t,  g_bn2_t);

    const int SM_MM  = 3 * 3 * MMG_ARR;   // A split + B = 3 arrays
    const int SM_ONE = 2 * 3 * MMG_ARR;   // A + B = 2 arrays
    cudaFuncSetAttribute((const void*)mma_gemm<1, false, true >,
                         cudaFuncAttributeMaxDynamicSharedMemorySize, SM_MM);
    cudaFuncSetAttribute((const void*)mma_gemm<6, true,  false>,
                         cudaFuncAttributeMaxDynamicSharedMemorySize, SM_ONE);
    cudaFuncSetAttribute((const void*)mma_gemm<3, false, false>,
                         cudaFuncAttributeMaxDynamicSharedMemorySize, SM_ONE);
    cudaFuncSetAttribute((const void*)mma_gemm<5, false, false>,
                         cudaFuncAttributeMaxDynamicSharedMemorySize, SM_ONE);

    // ---- fork: preps on side stream ----
    cudaEventRecord(g_ss.fork, 0);
    cudaStreamWaitEvent(g_ss.s, g_ss.fork, 0);
    prep_sq_kernel<<<(128 * 128 + 255) / 256, 256, 0, g_ss.s>>>(mm_W, p_mmWT);
    cudaEventRecord(g_ss.join2, g_ss.s);          // mm GEMM needs mmWT
    prep_bn_kernel<<<1, 512, 0, g_ss.s>>>(mlp_b1, bn1_g, bn1_b, bn1_rm, bn1_rv,
                                          mlp_b2, bn2_g, bn2_b, bn2_rm, bn2_rv);
    prep_w1_kernel<<<(512 * KC + 255) / 256, 256, 0, g_ss.s>>>(mlp_W1);
    prep_w2_kernel<<<(256 * 512 + 255) / 256, 256, 0, g_ss.s>>>(mlp_W2);
    prep_sq_kernel<<<(128 * 128 + 255) / 256, 256, 0, g_ss.s>>>(bi_W, p_biWT);
    cudaEventRecord(g_ss.join, g_ss.s);

    // ---- main chain ----
    split_xd_kernel<<<(Bsz * EDIM + 255) / 256, 256>>>(x_d128);
    cudaStreamWaitEvent(0, g_ss.join2, 0);

    // mm_pre = item_emb_d128 @ mm_W + mm_b   (A split; MODE 1)
    mma_gemm<1, false, true><<<dim3(1, Bsz / 128), 256, SM_MM>>>(
        p_xd_hi, p_xd_lo, p_mmWT, 128,
        nullptr, mm_b, p_mm_pre, nullptr, 128, nullptr);

    // per-row features -> c[:,0:640]
    features_kernel<<<Bsz, 256>>>(item_id, likes, views, item_seq,
                                  item_emb, cate_emb, ln_g, ln_b,
                                  se_W1, se_b1, se_W2, se_b2);

    cudaStreamWaitEvent(0, g_ss.join, 0);

    // xw = xs(fields 2..5, from c) @ bi_W -> fp16  (MODE 6, A_FROM_C)
    mma_gemm<6, true, false><<<dim3(1, (Bsz * 4) / 128), 256, SM_ONE>>>(
        p_c, nullptr, p_biWT, 128,
        nullptr, nullptr, nullptr, p_xw, 128, nullptr);

    // pair products -> c[:, 640:1920]  (all fp16)
    pairs_kernel<<<Bsz, 128>>>();

    // h1 = relu(bn1(c @ W1c^T + b1))   (MODE 3, K=1920)
    mma_gemm<3, false, false><<<dim3(512 / 128, Bsz / 128), 256, SM_ONE>>>(
        p_c, nullptr, p_W1T, KC,
        p_bn1_s, p_bn1_t, nullptr, p_h1, 512, nullptr);

    // h2+final: relu(bn2(h1 @ W2^T + b2)) . W3 -> partials (MODE 5)
    mma_gemm<5, false, false><<<dim3(256 / 128, Bsz / 128), 256, SM_ONE>>>(
        p_h1, nullptr, p_W2T, 512,
        p_bn2_s, p_bn2_t, p_part, nullptr, 4, mlp_W3);

    // logits -> sigmoid
    final_sig_kernel<<<(Bsz + 255) / 256, 256>>>(mlp_b3, out);
}

// round 14
// speedup vs baseline: 1.0982x; 1.0562x over previous
#include <cuda_runtime.h>
#include <cuda_fp16.h>
#include <math.h>
#include <stdint.h>

#define Bsz  16384
#define EDIM 128
#define HIST 50
#define KC   1920   // compact K for MLP1 (zero columns of c removed)
#define EPSF 1e-5f

// ---------------- scratch (device globals; no allocation allowed) ----------
__device__ float g_mm_pre[Bsz * EDIM];                       //  8.4 MB
__device__ __half g_xw[Bsz * 4 * EDIM];                      // 16.8 MB (fields 2..5 @ bi_W)
__device__ __half g_xd[Bsz * EDIM];                          //  4.2 MB (x_d128 fp16)
__device__ __half g_c[(size_t)Bsz * KC];                     // 63 MB (single fp16)
__device__ __half g_h1[Bsz * 512];                           // 16.8 MB
__device__ float g_part[Bsz * 4];                            // 256 KB logit partials
__device__ __half g_W1T[512 * KC];                           //  2 MB (N-major [512][1920])
__device__ __half g_W2T[256 * 512];
__device__ __half g_mmWT[128 * 128];
__device__ __half g_biWT[128 * 128];
__device__ float g_bn1_s[512], g_bn1_t[512];
__device__ float g_bn2_s[256], g_bn2_t[256];

// ---------------- side stream for prep overlap (created at load time) ------
struct SideStream {
    cudaStream_t s;
    cudaEvent_t  fork, join, join2;
    SideStream() {
        cudaStreamCreateWithFlags(&s, cudaStreamNonBlocking);
        cudaEventCreateWithFlags(&fork,  cudaEventDisableTiming);
        cudaEventCreateWithFlags(&join,  cudaEventDisableTiming);
        cudaEventCreateWithFlags(&join2, cudaEventDisableTiming);
    }
};
static SideStream g_ss;

// ================= PTX helpers (non-arch-specific only) =====================
__device__ __forceinline__ uint32_t smem_u32(const void* p) {
    uint32_t a;
    asm("{ .reg .u64 t; cvta.to.shared.u64 t, %1; cvt.u32.u64 %0, t; }"
        : "=r"(a) : "l"(p));
    return a;
}
__device__ __forceinline__ void cp_async16(uint32_t dst, const void* src) {
    asm volatile("cp.async.cg.shared.global [%0], [%1], 16;" :: "r"(dst), "l"(src));
}
#define CP_COMMIT() asm volatile("cp.async.commit_group;" ::: "memory")
#define CP_WAIT0()  asm volatile("cp.async.wait_group 0;" ::: "memory")
#define CP_WAIT1()  asm volatile("cp.async.wait_group 1;" ::: "memory")

__device__ __forceinline__ void ldsm_x4(uint32_t* r, uint32_t addr) {
    asm volatile("ldmatrix.sync.aligned.m8n8.x4.shared.b16 {%0,%1,%2,%3}, [%4];"
                 : "=r"(r[0]), "=r"(r[1]), "=r"(r[2]), "=r"(r[3]) : "r"(addr));
}
#define MMA_F16(c, a, b0v, b1v) \
    asm volatile("mma.sync.aligned.m16n8k16.row.col.f32.f16.f16.f32 " \
        "{%0,%1,%2,%3}, {%4,%5,%6,%7}, {%8,%9}, {%0,%1,%2,%3};" \
        : "+f"((c)[0]), "+f"((c)[1]), "+f"((c)[2]), "+f"((c)[3]) \
        : "r"((a)[0]), "r"((a)[1]), "r"((a)[2]), "r"((a)[3]), "r"(b0v), "r"(b1v))

// XOR-swizzled smem addressing: 128 rows x 64 B (32 fp16). unit = 16B column.
__device__ __forceinline__ uint32_t swz(int row, int unit) {
    return (uint32_t)(row * 64 + ((unit ^ ((row >> 1) & 3)) << 4));
}

// ---------------- prep kernels ----------------------------------------------
__global__ void prep_bn_kernel(const float* __restrict__ b1, const float* __restrict__ g1,
                               const float* __restrict__ be1, const float* __restrict__ rm1,
                               const float* __restrict__ rv1,
                               const float* __restrict__ b2, const float* __restrict__ g2,
                               const float* __restrict__ be2, const float* __restrict__ rm2,
                               const float* __restrict__ rv2) {
    int i = blockIdx.x * blockDim.x + threadIdx.x;
    if (i < 512) {
        float s = g1[i] * rsqrtf(rv1[i] + EPSF);
        g_bn1_s[i] = s;
        g_bn1_t[i] = (b1[i] - rm1[i]) * s + be1[i];
    }
    if (i < 256) {
        float s = g2[i] * rsqrtf(rv2[i] + EPSF);
        g_bn2_s[i] = s;
        g_bn2_t[i] = (b2[i] - rm2[i]) * s + be2[i];
    }
}

__global__ void prep_w1_kernel(const float* __restrict__ W1) {
    int idx = blockIdx.x * blockDim.x + threadIdx.x;
    if (idx >= 512 * KC) return;
    int n = idx / KC;
    int k = idx % KC;
    int orig = (k < 640) ? (k + 128) : (k + 768);
    g_W1T[idx] = __float2half_rn(W1[(size_t)orig * 512 + n]);
}

__global__ void prep_w2_kernel(const float* __restrict__ W2) {
    int idx = blockIdx.x * blockDim.x + threadIdx.x;
    if (idx >= 256 * 512) return;
    int n = idx / 512;
    int k = idx % 512;
    g_W2T[idx] = __float2half_rn(W2[(size_t)k * 256 + n]);
}

__global__ void prep_sq_kernel(const float* __restrict__ W, __half* __restrict__ T) {
    int idx = blockIdx.x * blockDim.x + threadIdx.x;
    if (idx >= 128 * 128) return;
    int n = idx >> 7;
    int k = idx & 127;
    T[idx] = __float2half_rn(W[k * 128 + n]);
}

__global__ void split_xd_kernel(const float* __restrict__ x) {
    int idx = blockIdx.x * blockDim.x + threadIdx.x;
    if (idx >= Bsz * EDIM) return;
    g_xd[idx] = __float2half_rn(x[idx]);
}

// ======== mma.sync fp16 GEMM: C = epi(A@B^T) ================================
// CTA tile 128x128, 8 warps (4m x 2n), BK=32, 3-stage cp.async, 2 CTAs/SM,
// XOR-swizzled smem, pass-outer MMA ordering, ONE __syncthreads per K-chunk.
// MODE: 1 = fp32 + shift (mm);
//       3 = fp16 out + scale/shift + relu (h1);
//       5 = scale/shift + relu + fused W3 dot -> per-CTA partials (h2+final);
//       6 = plain fp16 out (xw)
// A_FROM_C: A rows are xs fields 2..5 stored inside c (row r -> c[r>>2, ((r&3)+1)*128 ...])
#define MMG_ARR 8192                          // 128 rows x 64 B per operand tile

template <int MODE, bool A_FROM_C>
__global__ void __launch_bounds__(256, 2)
mma_gemm(const __half* __restrict__ Ah,
         const __half* __restrict__ Bh,
         int K,
         const float* __restrict__ scale, const float* __restrict__ shift,
         float* __restrict__ Cf, __half* __restrict__ Ch, int ldC,
         const float* __restrict__ w3) {
    constexpr int STAGE = 2 * MMG_ARR;
    extern __shared__ char smem[];
    const uint32_t sbase = smem_u32(smem);
    const int tid    = threadIdx.x;
    const int wid    = tid >> 5;
    const int lane   = tid & 31;
    const int warp_m = wid & 3;
    const int warp_n = wid >> 2;
    const int m0     = blockIdx.y * 128;
    const int bcol   = blockIdx.x * 128;
    const int nch    = K >> 5;               // BK = 32

    float acc[2][8][4];
    #pragma unroll
    for (int a = 0; a < 2; a++)
        #pragma unroll
        for (int b = 0; b < 8; b++)
            #pragma unroll
            for (int c = 0; c < 4; c++) acc[a][b][c] = 0.0f;

    auto load_stage = [&](int st, int k0) {
        const uint32_t sdst = sbase + st * STAGE;
        #pragma unroll
        for (int i = 0; i < 4; i++) {
            int c   = tid + i * 256;
            int a   = c >> 9;                // 0 = A, 1 = B (uniform per i)
            int idx = c & 511;
            int r   = idx >> 2;
            int cc  = idx & 3;
            const __half* g;
            if (a == 0) {
                if (A_FROM_C) {
                    int rr = m0 + r;         // global row = b*4 + jf
                    g = Ah + (size_t)(rr >> 2) * KC + ((rr & 3) + 1) * 128 + k0 + cc * 8;
                } else {
                    g = Ah + (size_t)(m0 + r) * K + k0 + cc * 8;
                }
            } else {
                g = Bh + (size_t)(bcol + r) * K + k0 + cc * 8;
            }
            cp_async16(sdst + a * MMG_ARR + swz(r, cc), g);
        }
        CP_COMMIT();
    };

    load_stage(0, 0);
    if (nch > 1) load_stage(1, 32);

    const int lrow = lane & 15;
    const int lcol = lane >> 4;
    int st = 0;

    for (int ch = 0; ch < nch; ch++) {
        if (ch + 1 < nch) { CP_WAIT1(); } else { CP_WAIT0(); }
        __syncthreads();
        if (ch + 2 < nch) {
            int st2 = st + 2; if (st2 >= 3) st2 -= 3;
            load_stage(st2, (ch + 2) << 5);
        }

        const uint32_t sa = sbase + st * STAGE;
        const uint32_t sb = sa + MMG_ARR;

        #pragma unroll
        for (int kk = 0; kk < 2; kk++) {
            uint32_t ah[2][4];
            #pragma unroll
            for (int mt = 0; mt < 2; mt++) {
                int row = warp_m * 32 + mt * 16 + lrow;
                ldsm_x4(ah[mt], sa + swz(row, kk * 2 + lcol));
            }
            #pragma unroll
            for (int q = 0; q < 4; q++) {
                uint32_t bh[4];
                int row = warp_n * 64 + q * 16 + lrow;
                ldsm_x4(bh, sb + swz(row, kk * 2 + lcol));
                #pragma unroll
                for (int mt = 0; mt < 2; mt++)
                    #pragma unroll
                    for (int sl = 0; sl < 2; sl++)
                        MMA_F16(acc[mt][q * 2 + sl], ah[mt], bh[sl], bh[sl + 2]);
            }
        }
        st++; if (st >= 3) st = 0;
    }

    // ---- fused epilogue ----
    float part[2][2] = {{0.f, 0.f}, {0.f, 0.f}};
    #pragma unroll
    for (int mt = 0; mt < 2; mt++) {
        const int rbase = m0 + warp_m * 32 + mt * 16 + (lane >> 2);
        #pragma unroll
        for (int nt = 0; nt < 8; nt++) {
            const int col = bcol + warp_n * 64 + nt * 8 + (lane & 3) * 2;
            float s0 = 1.0f, s1 = 1.0f, t0 = 0.0f, t1 = 0.0f;
            if (MODE == 3 || MODE == 5) { s0 = scale[col]; s1 = scale[col + 1]; }
            if (MODE == 1 || MODE == 3 || MODE == 5) { t0 = shift[col]; t1 = shift[col + 1]; }
            #pragma unroll
            for (int h = 0; h < 2; h++) {
                const size_t row = (size_t)(rbase + h * 8);
                float v0 = acc[mt][nt][h * 2 + 0];
                float v1 = acc[mt][nt][h * 2 + 1];
                if (MODE == 3 || MODE == 5) {
                    v0 = fmaxf(v0 * s0 + t0, 0.0f);
                    v1 = fmaxf(v1 * s1 + t1, 0.0f);
                } else if (MODE == 1) {
                    v0 += t0; v1 += t1;
                }
                if (MODE == 3 || MODE == 6) {
                    *(__half2*)&Ch[row * ldC + col] =
                        __halves2half2(__float2half_rn(v0), __float2half_rn(v1));
                } else if (MODE == 5) {
                    part[mt][h] += v0 * w3[col] + v1 * w3[col + 1];
                } else {
                    float2 fv; fv.x = v0; fv.y = v1;
                    *(float2*)&Cf[row * ldC + col] = fv;
                }
            }
        }
    }
    if (MODE == 5) {
        #pragma unroll
        for (int mt = 0; mt < 2; mt++) {
            #pragma unroll
            for (int h = 0; h < 2; h++) {
                float p = part[mt][h];
                p += __shfl_xor_sync(0xffffffffu, p, 1);
                p += __shfl_xor_sync(0xffffffffu, p, 2);
                if ((lane & 3) == 0) {
                    const int row = m0 + warp_m * 32 + mt * 16 + (lane >> 2) + h * 8;
                    Cf[(size_t)row * 4 + blockIdx.x * 2 + warp_n] = p;
                }
            }
        }
    }
}

// ---------------- per-row feature construction (exact R11 form) -------------
__device__ __forceinline__ float block_sum_128(float v, float* sred) {
    int lane = threadIdx.x & 31, wid = threadIdx.x >> 5;
    #pragma unroll
    for (int o = 16; o; o >>= 1) v += __shfl_xor_sync(0xffffffffu, v, o);
    if (lane == 0) sred[wid] = v;
    __syncthreads();
    float s = sred[0] + sred[1] + sred[2] + sred[3];
    __syncthreads();
    return s;
}

__global__ void features_kernel(const int* __restrict__ item_id,
                                const int* __restrict__ likes,
                                const int* __restrict__ views,
                                const int* __restrict__ item_seq,
                                const float* __restrict__ item_emb,
                                const float* __restrict__ cate_emb,
                                const float* __restrict__ ln_g,
                                const float* __restrict__ ln_b,
                                const float* __restrict__ se_W1,
                                const float* __restrict__ se_b1,
                                const float* __restrict__ se_W2,
                                const float* __restrict__ se_b2) {
    __shared__ float sred[4];
    __shared__ float sh_hist[4][EDIM];
    __shared__ int   scnt[4];
    __shared__ int   s_idx[HIST];
    const int b    = blockIdx.x;
    const int tid  = threadIdx.x;
    const int wid  = tid >> 5;
    const int lane = tid & 31;

    if (tid < HIST) s_idx[tid] = item_seq[(size_t)b * HIST + tid];
    __syncthreads();

    {
        float4 hs = make_float4(0.f, 0.f, 0.f, 0.f);
        int c = 0;
        for (int t = wid; t < HIST; t += 4) {
            int s = s_idx[t];
            if (s != 0) {
                float4 v = ((const float4*)(item_emb + (size_t)s * EDIM))[lane];
                hs.x += v.x; hs.y += v.y; hs.z += v.z; hs.w += v.w;
                c++;
            }
        }
        ((float4*)sh_hist[wid])[lane] = hs;
        if (lane == 0) scnt[wid] = c;
    }
    __syncthreads();

    const int e = tid;
    float hsum = sh_hist[0][e] + sh_hist[1][e] + sh_hist[2][e] + sh_hist[3][e];
    int   cnt  = scnt[0] + scnt[1] + scnt[2] + scnt[3];
    float hist = hsum / (float)(cnt > 1 ? cnt : 1);
    __syncthreads();

    float mmv = g_mm_pre[(size_t)b * EDIM + e];
    float mu  = block_sum_128(mmv, sred) * (1.0f / 128.0f);
    float d   = mmv - mu;
    float var = block_sum_128(d * d, sred) * (1.0f / 128.0f);
    float mm  = fmaxf(d * rsqrtf(var + EPSF) * ln_g[e] + ln_b[e], 0.0f);

    int   id   = item_id[b];
    float item = (id == 0) ? 0.0f : item_emb[(size_t)id * EDIM + e];
    float like = cate_emb[(size_t)likes[b] * EDIM + e];
    float view = cate_emb[(size_t)views[b] * EDIM + e];

    float x[6] = {0.0f, like, view, item, mm, hist};

    float z[6];
    z[0] = 0.0f;
    #pragma unroll
    for (int f = 1; f < 6; f++) z[f] = block_sum_128(x[f], sred) * (1.0f / 128.0f);

    float w[6];
    {
        float h[3];
        #pragma unroll
        for (int j = 0; j < 3; j++) {
            float s = se_b1[j];
            #pragma unroll
            for (int f = 0; f < 6; f++) s += z[f] * se_W1[f * 3 + j];
            h[j] = fmaxf(s, 0.0f);
        }
        #pragma unroll
        for (int f = 0; f < 6; f++) {
            float s = se_b2[f];
            #pragma unroll
            for (int j = 0; j < 3; j++) s += h[j] * se_W2[j * 6 + f];
            w[f] = 1.0f / (1.0f + expf(-s));
        }
    }

    #pragma unroll
    for (int f = 1; f < 6; f++) {
        float xv = x[f] * w[f];
        g_c[(size_t)b * KC + (f - 1) * EDIM + e] = __float2half_rn(xv);
    }
}

// ---------------- bilinear pair products: all fp16 in/out -------------------
__global__ void pairs_kernel() {
    const int b = blockIdx.x;
    const int e = threadIdx.x;
    const size_t cb0 = (size_t)b * KC + e;
    float xs0 = __half2float(g_c[cb0]);
    float xs1 = __half2float(g_c[cb0 + EDIM]);
    float xs2 = __half2float(g_c[cb0 + 2 * EDIM]);
    float xs3 = __half2float(g_c[cb0 + 3 * EDIM]);
    const size_t x4 = (size_t)b * 4 * EDIM + e;
    float xw0 = __half2float(g_xw[x4]);
    float xw1 = __half2float(g_xw[x4 + EDIM]);
    float xw2 = __half2float(g_xw[x4 + 2 * EDIM]);
    float xw3 = __half2float(g_xw[x4 + 3 * EDIM]);
    float p[10] = { xs0 * xw0, xs0 * xw1, xs0 * xw2, xs0 * xw3,
                    xs1 * xw1, xs1 * xw2, xs1 * xw3,
                    xs2 * xw2, xs2 * xw3,
                    xs3 * xw3 };
    const size_t cb = cb0 + 640;
    #pragma unroll
    for (int pr = 0; pr < 10; pr++)
        g_c[cb + pr * EDIM] = __float2half_rn(p[pr]);
}

// ---------------- final: sum partials + bias + sigmoid ---------------------
__global__ void final_sig_kernel(const float* __restrict__ b3, float* __restrict__ out) {
    int b = blockIdx.x * blockDim.x + threadIdx.x;
    if (b >= Bsz) return;
    float l = g_part[b * 4] + g_part[b * 4 + 1] + g_part[b * 4 + 2] + g_part[b * 4 + 3]
            + b3[0];
    out[b] = 1.0f / (1.0f + expf(-l));
}

// ---------------- launch ----------------------------------------------------
extern "C" void kernel_launch(void* const* d_in, const int* in_sizes, int n_in,
                              void* d_out, int out_size) {
    const int*   item_id   = (const int*)  d_in[0];
    const float* x_d128    = (const float*)d_in[1];
    const int*   likes     = (const int*)  d_in[2];
    const int*   views     = (const int*)  d_in[3];
    const int*   item_seq  = (const int*)  d_in[4];
    const float* item_emb  = (const float*)d_in[5];
    const float* cate_emb  = (const float*)d_in[6];
    const float* mm_W      = (const float*)d_in[7];
    const float* mm_b      = (const float*)d_in[8];
    const float* ln_g      = (const float*)d_in[9];
    const float* ln_b      = (const float*)d_in[10];
    const float* se_W1     = (const float*)d_in[11];
    const float* se_b1     = (const float*)d_in[12];
    const float* se_W2     = (const float*)d_in[13];
    const float* se_b2     = (const float*)d_in[14];
    const float* bi_W      = (const float*)d_in[15];
    const float* mlp_W1    = (const float*)d_in[16];
    const float* mlp_b1    = (const float*)d_in[17];
    const float* bn1_g     = (const float*)d_in[18];
    const float* bn1_b     = (const float*)d_in[19];
    const float* bn1_rm    = (const float*)d_in[20];
    const float* bn1_rv    = (const float*)d_in[21];
    const float* mlp_W2    = (const float*)d_in[22];
    const float* mlp_b2    = (const float*)d_in[23];
    const float* bn2_g     = (const float*)d_in[24];
    const float* bn2_b     = (const float*)d_in[25];
    const float* bn2_rm    = (const float*)d_in[26];
    const float* bn2_rv    = (const float*)d_in[27];
    const float* mlp_W3    = (const float*)d_in[28];
    const float* mlp_b3    = (const float*)d_in[29];
    float*       out       = (float*)d_out;

    float *p_mm_pre, *p_part;
    float *p_bn1_s, *p_bn1_t, *p_bn2_s, *p_bn2_t;
    __half *p_c, *p_h1, *p_xw, *p_W1T, *p_W2T, *p_xd, *p_mmWT, *p_biWT;
    cudaGetSymbolAddress((void**)&p_mm_pre, g_mm_pre);
    cudaGetSymbolAddress((void**)&p_xw,     g_xw);
    cudaGetSymbolAddress((void**)&p_part,   g_part);
    cudaGetSymbolAddress((void**)&p_c,      g_c);
    cudaGetSymbolAddress((void**)&p_h1,     g_h1);
    cudaGetSymbolAddress((void**)&p_W1T,    g_W1T);
    cudaGetSymbolAddress((void**)&p_W2T,    g_W2T);
    cudaGetSymbolAddress((void**)&p_xd,     g_xd);
    cudaGetSymbolAddress((void**)&p_mmWT,   g_mmWT);
    cudaGetSymbolAddress((void**)&p_biWT,   g_biWT);
    cudaGetSymbolAddress((void**)&p_bn1_s,  g_bn1_s);
    cudaGetSymbolAddress((void**)&p_bn1_t,  g_bn1_t);
    cudaGetSymbolAddress((void**)&p_bn2_s,  g_bn2_s);
    cudaGetSymbolAddress((void**)&p_bn2_t,  g_bn2_t);

    const int SM_ONE = 2 * 3 * MMG_ARR;   // A + B = 2 arrays x 3 stages
    cudaFuncSetAttribute((const void*)mma_gemm<1, false>,
                         cudaFuncAttributeMaxDynamicSharedMemorySize, SM_ONE);
    cudaFuncSetAttribute((const void*)mma_gemm<6, true >,
                         cudaFuncAttributeMaxDynamicSharedMemorySize, SM_ONE);
    cudaFuncSetAttribute((const void*)mma_gemm<3, false>,
                         cudaFuncAttributeMaxDynamicSharedMemorySize, SM_ONE);
    cudaFuncSetAttribute((const void*)mma_gemm<5, false>,
                         cudaFuncAttributeMaxDynamicSharedMemorySize, SM_ONE);

    // ---- fork: preps on side stream ----
    cudaEventRecord(g_ss.fork, 0);
    cudaStreamWaitEvent(g_ss.s, g_ss.fork, 0);
    prep_sq_kernel<<<(128 * 128 + 255) / 256, 256, 0, g_ss.s>>>(mm_W, p_mmWT);
    cudaEventRecord(g_ss.join2, g_ss.s);          // mm GEMM needs mmWT
    prep_bn_kernel<<<1, 512, 0, g_ss.s>>>(mlp_b1, bn1_g, bn1_b, bn1_rm, bn1_rv,
                                          mlp_b2, bn2_g, bn2_b, bn2_rm, bn2_rv);
    prep_w1_kernel<<<(512 * KC + 255) / 256, 256, 0, g_ss.s>>>(mlp_W1);
    prep_w2_kernel<<<(256 * 512 + 255) / 256, 256, 0, g_ss.s>>>(mlp_W2);
    prep_sq_kernel<<<(128 * 128 + 255) / 256, 256, 0, g_ss.s>>>(bi_W, p_biWT);
    cudaEventRecord(g_ss.join, g_ss.s);

    // ---- main chain ----
    split_xd_kernel<<<(Bsz * EDIM + 255) / 256, 256>>>(x_d128);
    cudaStreamWaitEvent(0, g_ss.join2, 0);

    // mm_pre = item_emb_d128 @ mm_W + mm_b   (single-pass fp16; MODE 1)
    mma_gemm<1, false><<<dim3(1, Bsz / 128), 256, SM_ONE>>>(
        p_xd, p_mmWT, 128,
        nullptr, mm_b, p_mm_pre, nullptr, 128, nullptr);

    // per-row features -> c[:,0:640]
    features_kernel<<<Bsz, 128>>>(item_id, likes, views, item_seq,
                                  item_emb, cate_emb, ln_g, ln_b,
                                  se_W1, se_b1, se_W2, se_b2);

    cudaStreamWaitEvent(0, g_ss.join, 0);

    // xw = xs(fields 2..5, from c) @ bi_W -> fp16  (MODE 6, A_FROM_C)
    mma_gemm<6, true><<<dim3(1, (Bsz * 4) / 128), 256, SM_ONE>>>(
        p_c, p_biWT, 128,
        nullptr, nullptr, nullptr, p_xw, 128, nullptr);

    // pair products -> c[:, 640:1920]  (all fp16)
    pairs_kernel<<<Bsz, 128>>>();

    // h1 = relu(bn1(c @ W1c^T + b1))   (MODE 3, K=1920)
    mma_gemm<3, false><<<dim3(512 / 128, Bsz / 128), 256, SM_ONE>>>(
        p_c, p_W1T, KC,
        p_bn1_s, p_bn1_t, nullptr, p_h1, 512, nullptr);

    // h2+final: relu(bn2(h1 @ W2^T + b2)) . W3 -> partials (MODE 5)
    mma_gemm<5, false><<<dim3(256 / 128, Bsz / 128), 256, SM_ONE>>>(
        p_h1, p_W2T, 512,
        p_bn2_s, p_bn2_t, p_part, nullptr, 4, mlp_W3);

    // logits -> sigmoid
    final_sig_kernel<<<(Bsz + 255) / 256, 256>>>(mlp_b3, out);
}

// round 15
// speedup vs baseline: 1.1705x; 1.0659x over previous
#include <cuda_runtime.h>
#include <cuda_fp16.h>
#include <math.h>
#include <stdint.h>

#define Bsz  16384
#define EDIM 128
#define HIST 50
#define KC   1920   // compact K for MLP1 (zero columns of c removed)
#define EPSF 1e-5f

// ---------------- scratch (device globals; no allocation allowed) ----------
__device__ float g_mm_pre[Bsz * EDIM];                       //  8.4 MB
__device__ __half g_xw[Bsz * 4 * EDIM];                      // 16.8 MB (fields 2..5 @ bi_W)
__device__ __half g_xd[Bsz * EDIM];                          //  4.2 MB (x_d128 fp16)
__device__ __half g_c[(size_t)Bsz * KC];                     // 63 MB (single fp16)
__device__ __half g_h1[Bsz * 512];                           // 16.8 MB
__device__ float g_part[Bsz * 4];                            // 256 KB logit partials
__device__ __half g_W1T[512 * KC];                           //  2 MB (N-major [512][1920])
__device__ __half g_W2T[256 * 512];
__device__ __half g_mmWT[128 * 128];
__device__ __half g_biWT[128 * 128];
__device__ float g_bn1_s[512], g_bn1_t[512];
__device__ float g_bn2_s[256], g_bn2_t[256];

// ---------------- side stream for prep overlap (created at load time) ------
struct SideStream {
    cudaStream_t s;
    cudaEvent_t  fork, join, join2;
    SideStream() {
        cudaStreamCreateWithFlags(&s, cudaStreamNonBlocking);
        cudaEventCreateWithFlags(&fork,  cudaEventDisableTiming);
        cudaEventCreateWithFlags(&join,  cudaEventDisableTiming);
        cudaEventCreateWithFlags(&join2, cudaEventDisableTiming);
    }
};
static SideStream g_ss;

// ================= PTX helpers (non-arch-specific only) =====================
__device__ __forceinline__ uint32_t smem_u32(const void* p) {
    uint32_t a;
    asm("{ .reg .u64 t; cvta.to.shared.u64 t, %1; cvt.u32.u64 %0, t; }"
        : "=r"(a) : "l"(p));
    return a;
}
__device__ __forceinline__ void cp_async16(uint32_t dst, const void* src) {
    asm volatile("cp.async.cg.shared.global [%0], [%1], 16;" :: "r"(dst), "l"(src));
}
#define CP_COMMIT() asm volatile("cp.async.commit_group;" ::: "memory")
#define CP_WAIT0()  asm volatile("cp.async.wait_group 0;" ::: "memory")
#define CP_WAIT1()  asm volatile("cp.async.wait_group 1;" ::: "memory")

__device__ __forceinline__ void ldsm_x4(uint32_t* r, uint32_t addr) {
    asm volatile("ldmatrix.sync.aligned.m8n8.x4.shared.b16 {%0,%1,%2,%3}, [%4];"
                 : "=r"(r[0]), "=r"(r[1]), "=r"(r[2]), "=r"(r[3]) : "r"(addr));
}
#define MMA_F16(c, a, b0v, b1v) \
    asm volatile("mma.sync.aligned.m16n8k16.row.col.f32.f16.f16.f32 " \
        "{%0,%1,%2,%3}, {%4,%5,%6,%7}, {%8,%9}, {%0,%1,%2,%3};" \
        : "+f"((c)[0]), "+f"((c)[1]), "+f"((c)[2]), "+f"((c)[3]) \
        : "r"((a)[0]), "r"((a)[1]), "r"((a)[2]), "r"((a)[3]), "r"(b0v), "r"(b1v))

// XOR-swizzled smem addressing: 128 rows x 128 B (64 fp16). unit = 16B column (0..7).
// Conflict-free for cp.async row-major stores AND ldmatrix 8-row phases.
__device__ __forceinline__ uint32_t swz(int row, int unit) {
    return (uint32_t)(row * 128 + ((unit ^ (row & 7)) << 4));
}

// ---------------- prep kernels ----------------------------------------------
__global__ void prep_bn_kernel(const float* __restrict__ b1, const float* __restrict__ g1,
                               const float* __restrict__ be1, const float* __restrict__ rm1,
                               const float* __restrict__ rv1,
                               const float* __restrict__ b2, const float* __restrict__ g2,
                               const float* __restrict__ be2, const float* __restrict__ rm2,
                               const float* __restrict__ rv2) {
    int i = blockIdx.x * blockDim.x + threadIdx.x;
    if (i < 512) {
        float s = g1[i] * rsqrtf(rv1[i] + EPSF);
        g_bn1_s[i] = s;
        g_bn1_t[i] = (b1[i] - rm1[i]) * s + be1[i];
    }
    if (i < 256) {
        float s = g2[i] * rsqrtf(rv2[i] + EPSF);
        g_bn2_s[i] = s;
        g_bn2_t[i] = (b2[i] - rm2[i]) * s + be2[i];
    }
}

__global__ void prep_w1_kernel(const float* __restrict__ W1) {
    int idx = blockIdx.x * blockDim.x + threadIdx.x;
    if (idx >= 512 * KC) return;
    int n = idx / KC;
    int k = idx % KC;
    int orig = (k < 640) ? (k + 128) : (k + 768);
    g_W1T[idx] = __float2half_rn(W1[(size_t)orig * 512 + n]);
}

__global__ void prep_w2_kernel(const float* __restrict__ W2) {
    int idx = blockIdx.x * blockDim.x + threadIdx.x;
    if (idx >= 256 * 512) return;
    int n = idx / 512;
    int k = idx % 512;
    g_W2T[idx] = __float2half_rn(W2[(size_t)k * 256 + n]);
}

__global__ void prep_sq_kernel(const float* __restrict__ W, __half* __restrict__ T) {
    int idx = blockIdx.x * blockDim.x + threadIdx.x;
    if (idx >= 128 * 128) return;
    int n = idx >> 7;
    int k = idx & 127;
    T[idx] = __float2half_rn(W[k * 128 + n]);
}

__global__ void split_xd_kernel(const float* __restrict__ x) {
    int idx = blockIdx.x * blockDim.x + threadIdx.x;
    if (idx >= Bsz * EDIM) return;
    g_xd[idx] = __float2half_rn(x[idx]);
}

// ======== mma.sync fp16 GEMM: C = epi(A@B^T) ================================
// CTA tile 128x128, 8 warps (4m x 2n), BK=64, 3-stage cp.async, 2 CTAs/SM,
// XOR-swizzled smem (128B rows), pass-outer MMA ordering,
// ONE __syncthreads per K-chunk (half the barriers of BK=32).
// MODE: 1 = fp32 + shift (mm);
//       3 = fp16 out + scale/shift + relu (h1);
//       5 = scale/shift + relu + fused W3 dot -> per-CTA partials (h2+final);
//       6 = plain fp16 out (xw)
// A_FROM_C: A rows are xs fields 2..5 stored inside c (row r -> c[r>>2, ((r&3)+1)*128 ...])
#define MMG_ARR 16384                         // 128 rows x 128 B per operand tile
#define MMG_SMEM (3 * 2 * MMG_ARR)            // 98304 B

template <int MODE, bool A_FROM_C>
__global__ void __launch_bounds__(256, 2)
mma_gemm(const __half* __restrict__ Ah,
         const __half* __restrict__ Bh,
         int K,
         const float* __restrict__ scale, const float* __restrict__ shift,
         float* __restrict__ Cf, __half* __restrict__ Ch, int ldC,
         const float* __restrict__ w3) {
    constexpr int STAGE = 2 * MMG_ARR;
    extern __shared__ char smem[];
    const uint32_t sbase = smem_u32(smem);
    const int tid    = threadIdx.x;
    const int wid    = tid >> 5;
    const int lane   = tid & 31;
    const int warp_m = wid & 3;
    const int warp_n = wid >> 2;
    const int m0     = blockIdx.y * 128;
    const int bcol   = blockIdx.x * 128;
    const int nch    = K >> 6;               // BK = 64

    float acc[2][8][4];
    #pragma unroll
    for (int a = 0; a < 2; a++)
        #pragma unroll
        for (int b = 0; b < 8; b++)
            #pragma unroll
            for (int c = 0; c < 4; c++) acc[a][b][c] = 0.0f;

    auto load_stage = [&](int st, int k0) {
        const uint32_t sdst = sbase + st * STAGE;
        #pragma unroll
        for (int i = 0; i < 8; i++) {
            int c   = tid + i * 256;
            int a   = c >> 10;               // 0 = A, 1 = B (uniform per i)
            int idx = c & 1023;
            int r   = idx >> 3;
            int cc  = idx & 7;
            const __half* g;
            if (a == 0) {
                if (A_FROM_C) {
                    int rr = m0 + r;         // global row = b*4 + jf
                    g = Ah + (size_t)(rr >> 2) * KC + ((rr & 3) + 1) * 128 + k0 + cc * 8;
                } else {
                    g = Ah + (size_t)(m0 + r) * K + k0 + cc * 8;
                }
            } else {
                g = Bh + (size_t)(bcol + r) * K + k0 + cc * 8;
            }
            cp_async16(sdst + a * MMG_ARR + swz(r, cc), g);
        }
        CP_COMMIT();
    };

    load_stage(0, 0);
    if (nch > 1) load_stage(1, 64);

    const int lrow = lane & 15;
    const int lcol = lane >> 4;
    int st = 0;

    for (int ch = 0; ch < nch; ch++) {
        if (ch + 1 < nch) { CP_WAIT1(); } else { CP_WAIT0(); }
        __syncthreads();
        if (ch + 2 < nch) {
            int st2 = st + 2; if (st2 >= 3) st2 -= 3;
            load_stage(st2, (ch + 2) << 6);
        }

        const uint32_t sa = sbase + st * STAGE;
        const uint32_t sb = sa + MMG_ARR;

        #pragma unroll
        for (int kk = 0; kk < 4; kk++) {
            uint32_t ah[2][4];
            #pragma unroll
            for (int mt = 0; mt < 2; mt++) {
                int row = warp_m * 32 + mt * 16 + lrow;
                ldsm_x4(ah[mt], sa + swz(row, kk * 2 + lcol));
            }
            #pragma unroll
            for (int q = 0; q < 4; q++) {
                uint32_t bh[4];
                int row = warp_n * 64 + q * 16 + lrow;
                ldsm_x4(bh, sb + swz(row, kk * 2 + lcol));
                #pragma unroll
                for (int mt = 0; mt < 2; mt++)
                    #pragma unroll
                    for (int sl = 0; sl < 2; sl++)
                        MMA_F16(acc[mt][q * 2 + sl], ah[mt], bh[sl], bh[sl + 2]);
            }
        }
        st++; if (st >= 3) st = 0;
    }

    // ---- fused epilogue ----
    float part[2][2] = {{0.f, 0.f}, {0.f, 0.f}};
    #pragma unroll
    for (int mt = 0; mt < 2; mt++) {
        const int rbase = m0 + warp_m * 32 + mt * 16 + (lane >> 2);
        #pragma unroll
        for (int nt = 0; nt < 8; nt++) {
            const int col = bcol + warp_n * 64 + nt * 8 + (lane & 3) * 2;
            float s0 = 1.0f, s1 = 1.0f, t0 = 0.0f, t1 = 0.0f;
            if (MODE == 3 || MODE == 5) { s0 = scale[col]; s1 = scale[col + 1]; }
            if (MODE == 1 || MODE == 3 || MODE == 5) { t0 = shift[col]; t1 = shift[col + 1]; }
            #pragma unroll
            for (int h = 0; h < 2; h++) {
                const size_t row = (size_t)(rbase + h * 8);
                float v0 = acc[mt][nt][h * 2 + 0];
                float v1 = acc[mt][nt][h * 2 + 1];
                if (MODE == 3 || MODE == 5) {
                    v0 = fmaxf(v0 * s0 + t0, 0.0f);
                    v1 = fmaxf(v1 * s1 + t1, 0.0f);
                } else if (MODE == 1) {
                    v0 += t0; v1 += t1;
                }
                if (MODE == 3 || MODE == 6) {
                    *(__half2*)&Ch[row * ldC + col] =
                        __halves2half2(__float2half_rn(v0), __float2half_rn(v1));
                } else if (MODE == 5) {
                    part[mt][h] += v0 * w3[col] + v1 * w3[col + 1];
                } else {
                    float2 fv; fv.x = v0; fv.y = v1;
                    *(float2*)&Cf[row * ldC + col] = fv;
                }
            }
        }
    }
    if (MODE == 5) {
        #pragma unroll
        for (int mt = 0; mt < 2; mt++) {
            #pragma unroll
            for (int h = 0; h < 2; h++) {
                float p = part[mt][h];
                p += __shfl_xor_sync(0xffffffffu, p, 1);
                p += __shfl_xor_sync(0xffffffffu, p, 2);
                if ((lane & 3) == 0) {
                    const int row = m0 + warp_m * 32 + mt * 16 + (lane >> 2) + h * 8;
                    Cf[(size_t)row * 4 + blockIdx.x * 2 + warp_n] = p;
                }
            }
        }
    }
}

// ---------------- per-row feature construction (exact R11 form) -------------
__device__ __forceinline__ float block_sum_128(float v, float* sred) {
    int lane = threadIdx.x & 31, wid = threadIdx.x >> 5;
    #pragma unroll
    for (int o = 16; o; o >>= 1) v += __shfl_xor_sync(0xffffffffu, v, o);
    if (lane == 0) sred[wid] = v;
    __syncthreads();
    float s = sred[0] + sred[1] + sred[2] + sred[3];
    __syncthreads();
    return s;
}

__global__ void features_kernel(const int* __restrict__ item_id,
                                const int* __restrict__ likes,
                                const int* __restrict__ views,
                                const int* __restrict__ item_seq,
                                const float* __restrict__ item_emb,
                                const float* __restrict__ cate_emb,
                                const float* __restrict__ ln_g,
                                const float* __restrict__ ln_b,
                                const float* __restrict__ se_W1,
                                const float* __restrict__ se_b1,
                                const float* __restrict__ se_W2,
                                const float* __restrict__ se_b2) {
    __shared__ float sred[4];
    __shared__ float sh_hist[4][EDIM];
    __shared__ int   scnt[4];
    __shared__ int   s_idx[HIST];
    const int b    = blockIdx.x;
    const int tid  = threadIdx.x;
    const int wid  = tid >> 5;
    const int lane = tid & 31;

    if (tid < HIST) s_idx[tid] = item_seq[(size_t)b * HIST + tid];
    __syncthreads();

    {
        float4 hs = make_float4(0.f, 0.f, 0.f, 0.f);
        int c = 0;
        for (int t = wid; t < HIST; t += 4) {
            int s = s_idx[t];
            if (s != 0) {
                float4 v = ((const float4*)(item_emb + (size_t)s * EDIM))[lane];
                hs.x += v.x; hs.y += v.y; hs.z += v.z; hs.w += v.w;
                c++;
            }
        }
        ((float4*)sh_hist[wid])[lane] = hs;
        if (lane == 0) scnt[wid] = c;
    }
    __syncthreads();

    const int e = tid;
    float hsum = sh_hist[0][e] + sh_hist[1][e] + sh_hist[2][e] + sh_hist[3][e];
    int   cnt  = scnt[0] + scnt[1] + scnt[2] + scnt[3];
    float hist = hsum / (float)(cnt > 1 ? cnt : 1);
    __syncthreads();

    float mmv = g_mm_pre[(size_t)b * EDIM + e];
    float mu  = block_sum_128(mmv, sred) * (1.0f / 128.0f);
    float d   = mmv - mu;
    float var = block_sum_128(d * d, sred) * (1.0f / 128.0f);
    float mm  = fmaxf(d * rsqrtf(var + EPSF) * ln_g[e] + ln_b[e], 0.0f);

    int   id   = item_id[b];
    float item = (id == 0) ? 0.0f : item_emb[(size_t)id * EDIM + e];
    float like = cate_emb[(size_t)likes[b] * EDIM + e];
    float view = cate_emb[(size_t)views[b] * EDIM + e];

    float x[6] = {0.0f, like, view, item, mm, hist};

    float z[6];
    z[0] = 0.0f;
    #pragma unroll
    for (int f = 1; f < 6; f++) z[f] = block_sum_128(x[f], sred) * (1.0f / 128.0f);

    float w[6];
    {
        float h[3];
        #pragma unroll
        for (int j = 0; j < 3; j++) {
            float s = se_b1[j];
            #pragma unroll
            for (int f = 0; f < 6; f++) s += z[f] * se_W1[f * 3 + j];
            h[j] = fmaxf(s, 0.0f);
        }
        #pragma unroll
        for (int f = 0; f < 6; f++) {
            float s = se_b2[f];
            #pragma unroll
            for (int j = 0; j < 3; j++) s += h[j] * se_W2[j * 6 + f];
            w[f] = 1.0f / (1.0f + expf(-s));
        }
    }

    #pragma unroll
    for (int f = 1; f < 6; f++) {
        float xv = x[f] * w[f];
        g_c[(size_t)b * KC + (f - 1) * EDIM + e] = __float2half_rn(xv);
    }
}

// ---------------- bilinear pair products: all fp16 in/out -------------------
__global__ void pairs_kernel() {
    const int b = blockIdx.x;
    const int e = threadIdx.x;
    const size_t cb0 = (size_t)b * KC + e;
    float xs0 = __half2float(g_c[cb0]);
    float xs1 = __half2float(g_c[cb0 + EDIM]);
    float xs2 = __half2float(g_c[cb0 + 2 * EDIM]);
    float xs3 = __half2float(g_c[cb0 + 3 * EDIM]);
    const size_t x4 = (size_t)b * 4 * EDIM + e;
    float xw0 = __half2float(g_xw[x4]);
    float xw1 = __half2float(g_xw[x4 + EDIM]);
    float xw2 = __half2float(g_xw[x4 + 2 * EDIM]);
    float xw3 = __half2float(g_xw[x4 + 3 * EDIM]);
    float p[10] = { xs0 * xw0, xs0 * xw1, xs0 * xw2, xs0 * xw3,
                    xs1 * xw1, xs1 * xw2, xs1 * xw3,
                    xs2 * xw2, xs2 * xw3,
                    xs3 * xw3 };
    const size_t cb = cb0 + 640;
    #pragma unroll
    for (int pr = 0; pr < 10; pr++)
        g_c[cb + pr * EDIM] = __float2half_rn(p[pr]);
}

// ---------------- final: sum partials + bias + sigmoid ---------------------
__global__ void final_sig_kernel(const float* __restrict__ b3, float* __restrict__ out) {
    int b = blockIdx.x * blockDim.x + threadIdx.x;
    if (b >= Bsz) return;
    float l = g_part[b * 4] + g_part[b * 4 + 1] + g_part[b * 4 + 2] + g_part[b * 4 + 3]
            + b3[0];
    out[b] = 1.0f / (1.0f + expf(-l));
}

// ---------------- launch ----------------------------------------------------
extern "C" void kernel_launch(void* const* d_in, const int* in_sizes, int n_in,
                              void* d_out, int out_size) {
    const int*   item_id   = (const int*)  d_in[0];
    const float* x_d128    = (const float*)d_in[1];
    const int*   likes     = (const int*)  d_in[2];
    const int*   views     = (const int*)  d_in[3];
    const int*   item_seq  = (const int*)  d_in[4];
    const float* item_emb  = (const float*)d_in[5];
    const float* cate_emb  = (const float*)d_in[6];
    const float* mm_W      = (const float*)d_in[7];
    const float* mm_b      = (const float*)d_in[8];
    const float* ln_g      = (const float*)d_in[9];
    const float* ln_b      = (const float*)d_in[10];
    const float* se_W1     = (const float*)d_in[11];
    const float* se_b1     = (const float*)d_in[12];
    const float* se_W2     = (const float*)d_in[13];
    const float* se_b2     = (const float*)d_in[14];
    const float* bi_W      = (const float*)d_in[15];
    const float* mlp_W1    = (const float*)d_in[16];
    const float* mlp_b1    = (const float*)d_in[17];
    const float* bn1_g     = (const float*)d_in[18];
    const float* bn1_b     = (const float*)d_in[19];
    const float* bn1_rm    = (const float*)d_in[20];
    const float* bn1_rv    = (const float*)d_in[21];
    const float* mlp_W2    = (const float*)d_in[22];
    const float* mlp_b2    = (const float*)d_in[23];
    const float* bn2_g     = (const float*)d_in[24];
    const float* bn2_b     = (const float*)d_in[25];
    const float* bn2_rm    = (const float*)d_in[26];
    const float* bn2_rv    = (const float*)d_in[27];
    const float* mlp_W3    = (const float*)d_in[28];
    const float* mlp_b3    = (const float*)d_in[29];
    float*       out       = (float*)d_out;

    float *p_mm_pre, *p_part;
    float *p_bn1_s, *p_bn1_t, *p_bn2_s, *p_bn2_t;
    __half *p_c, *p_h1, *p_xw, *p_W1T, *p_W2T, *p_xd, *p_mmWT, *p_biWT;
    cudaGetSymbolAddress((void**)&p_mm_pre, g_mm_pre);
    cudaGetSymbolAddress((void**)&p_xw,     g_xw);
    cudaGetSymbolAddress((void**)&p_part,   g_part);
    cudaGetSymbolAddress((void**)&p_c,      g_c);
    cudaGetSymbolAddress((void**)&p_h1,     g_h1);
    cudaGetSymbolAddress((void**)&p_W1T,    g_W1T);
    cudaGetSymbolAddress((void**)&p_W2T,    g_W2T);
    cudaGetSymbolAddress((void**)&p_xd,     g_xd);
    cudaGetSymbolAddress((void**)&p_mmWT,   g_mmWT);
    cudaGetSymbolAddress((void**)&p_biWT,   g_biWT);
    cudaGetSymbolAddress((void**)&p_bn1_s,  g_bn1_s);
    cudaGetSymbolAddress((void**)&p_bn1_t,  g_bn1_t);
    cudaGetSymbolAddress((void**)&p_bn2_s,  g_bn2_s);
    cudaGetSymbolAddress((void**)&p_bn2_t,  g_bn2_t);

    cudaFuncSetAttribute((const void*)mma_gemm<1, false>,
                         cudaFuncAttributeMaxDynamicSharedMemorySize, MMG_SMEM);
    cudaFuncSetAttribute((const void*)mma_gemm<6, true >,
                         cudaFuncAttributeMaxDynamicSharedMemorySize, MMG_SMEM);
    cudaFuncSetAttribute((const void*)mma_gemm<3, false>,
                         cudaFuncAttributeMaxDynamicSharedMemorySize, MMG_SMEM);
    cudaFuncSetAttribute((const void*)mma_gemm<5, false>,
                         cudaFuncAttributeMaxDynamicSharedMemorySize, MMG_SMEM);

    // ---- fork: preps on side stream ----
    cudaEventRecord(g_ss.fork, 0);
    cudaStreamWaitEvent(g_ss.s, g_ss.fork, 0);
    prep_sq_kernel<<<(128 * 128 + 255) / 256, 256, 0, g_ss.s>>>(mm_W, p_mmWT);
    cudaEventRecord(g_ss.join2, g_ss.s);          // mm GEMM needs mmWT
    prep_bn_kernel<<<1, 512, 0, g_ss.s>>>(mlp_b1, bn1_g, bn1_b, bn1_rm, bn1_rv,
                                          mlp_b2, bn2_g, bn2_b, bn2_rm, bn2_rv);
    prep_w1_kernel<<<(512 * KC + 255) / 256, 256, 0, g_ss.s>>>(mlp_W1);
    prep_w2_kernel<<<(256 * 512 + 255) / 256, 256, 0, g_ss.s>>>(mlp_W2);
    prep_sq_kernel<<<(128 * 128 + 255) / 256, 256, 0, g_ss.s>>>(bi_W, p_biWT);
    cudaEventRecord(g_ss.join, g_ss.s);

    // ---- main chain ----
    split_xd_kernel<<<(Bsz * EDIM + 255) / 256, 256>>>(x_d128);
    cudaStreamWaitEvent(0, g_ss.join2, 0);

    // mm_pre = item_emb_d128 @ mm_W + mm_b   (single-pass fp16; MODE 1)
    mma_gemm<1, false><<<dim3(1, Bsz / 128), 256, MMG_SMEM>>>(
        p_xd, p_mmWT, 128,
        nullptr, mm_b, p_mm_pre, nullptr, 128, nullptr);

    // per-row features -> c[:,0:640]
    features_kernel<<<Bsz, 128>>>(item_id, likes, views, item_seq,
                                  item_emb, cate_emb, ln_g, ln_b,
                                  se_W1, se_b1, se_W2, se_b2);

    cudaStreamWaitEvent(0, g_ss.join, 0);

    // xw = xs(fields 2..5, from c) @ bi_W -> fp16  (MODE 6, A_FROM_C)
    mma_gemm<6, true><<<dim3(1, (Bsz * 4) / 128), 256, MMG_SMEM>>>(
        p_c, p_biWT, 128,
        nullptr, nullptr, nullptr, p_xw, 128, nullptr);

    // pair products -> c[:, 640:1920]  (all fp16)
    pairs_kernel<<<Bsz, 128>>>();

    // h1 = relu(bn1(c @ W1c^T + b1))   (MODE 3, K=1920)
    mma_gemm<3, false><<<dim3(512 / 128, Bsz / 128), 256, MMG_SMEM>>>(
        p_c, p_W1T, KC,
        p_bn1_s, p_bn1_t, nullptr, p_h1, 512, nullptr);

    // h2+final: relu(bn2(h1 @ W2^T + b2)) . W3 -> partials (MODE 5)
    mma_gemm<5, false><<<dim3(256 / 128, Bsz / 128), 256, MMG_SMEM>>>(
        p_h1, p_W2T, 512,
        p_bn2_s, p_bn2_t, p_part, nullptr, 4, mlp_W3);

    // logits -> sigmoid
    final_sig_kernel<<<(Bsz + 255) / 256, 256>>>(mlp_b3, out);
}

// round 16
// speedup vs baseline: 1.1767x; 1.0053x over previous
#include <cuda_runtime.h>
#include <cuda_fp16.h>
#include <math.h>
#include <stdint.h>

#define Bsz  16384
#define EDIM 128
#define HIST 50
#define KC   1920   // compact K for MLP1 (zero columns of c removed)
#define EPSF 1e-5f

// ---------------- scratch (device globals; no allocation allowed) ----------
__device__ float g_mm_pre[Bsz * EDIM];                       //  8.4 MB
__device__ __half g_xw[Bsz * 4 * EDIM];                      // 16.8 MB (fields 2..5 @ bi_W)
__device__ __half g_xd[Bsz * EDIM];                          //  4.2 MB (x_d128 fp16)
__device__ __half g_c[(size_t)Bsz * KC];                     // 63 MB (single fp16)
__device__ __half g_h1[Bsz * 512];                           // 16.8 MB
__device__ float g_part[Bsz * 4];                            // 256 KB logit partials
__device__ __half g_W1T[512 * KC];                           //  2 MB (N-major [512][1920])
__device__ __half g_W2T[256 * 512];
__device__ __half g_mmWT[128 * 128];
__device__ __half g_biWT[128 * 128];
__device__ float g_bn1_s[512], g_bn1_t[512];
__device__ float g_bn2_s[256], g_bn2_t[256];

// ---------------- side stream for prep overlap (created at load time) ------
struct SideStream {
    cudaStream_t s;
    cudaEvent_t  fork, join, join2;
    SideStream() {
        cudaStreamCreateWithFlags(&s, cudaStreamNonBlocking);
        cudaEventCreateWithFlags(&fork,  cudaEventDisableTiming);
        cudaEventCreateWithFlags(&join,  cudaEventDisableTiming);
        cudaEventCreateWithFlags(&join2, cudaEventDisableTiming);
    }
};
static SideStream g_ss;

// ================= PTX helpers (non-arch-specific only) =====================
__device__ __forceinline__ uint32_t smem_u32(const void* p) {
    uint32_t a;
    asm("{ .reg .u64 t; cvta.to.shared.u64 t, %1; cvt.u32.u64 %0, t; }"
        : "=r"(a) : "l"(p));
    return a;
}
__device__ __forceinline__ void cp_async16(uint32_t dst, const void* src) {
    asm volatile("cp.async.cg.shared.global [%0], [%1], 16;" :: "r"(dst), "l"(src));
}
#define CP_COMMIT() asm volatile("cp.async.commit_group;" ::: "memory")
#define CP_WAIT0()  asm volatile("cp.async.wait_group 0;" ::: "memory")
#define CP_WAIT1()  asm volatile("cp.async.wait_group 1;" ::: "memory")

__device__ __forceinline__ void ldsm_x4(uint32_t* r, uint32_t addr) {
    asm volatile("ldmatrix.sync.aligned.m8n8.x4.shared.b16 {%0,%1,%2,%3}, [%4];"
                 : "=r"(r[0]), "=r"(r[1]), "=r"(r[2]), "=r"(r[3]) : "r"(addr));
}
#define MMA_F16(c, a, b0v, b1v) \
    asm volatile("mma.sync.aligned.m16n8k16.row.col.f32.f16.f16.f32 " \
        "{%0,%1,%2,%3}, {%4,%5,%6,%7}, {%8,%9}, {%0,%1,%2,%3};" \
        : "+f"((c)[0]), "+f"((c)[1]), "+f"((c)[2]), "+f"((c)[3]) \
        : "r"((a)[0]), "r"((a)[1]), "r"((a)[2]), "r"((a)[3]), "r"(b0v), "r"(b1v))

// XOR-swizzled smem addressing: 128 rows x 128 B (64 fp16). unit = 16B column (0..7).
__device__ __forceinline__ uint32_t swz(int row, int unit) {
    return (uint32_t)(row * 128 + ((unit ^ (row & 7)) << 4));
}

// ---------------- prep kernels ----------------------------------------------
__global__ void prep_bn_kernel(const float* __restrict__ b1, const float* __restrict__ g1,
                               const float* __restrict__ be1, const float* __restrict__ rm1,
                               const float* __restrict__ rv1,
                               const float* __restrict__ b2, const float* __restrict__ g2,
                               const float* __restrict__ be2, const float* __restrict__ rm2,
                               const float* __restrict__ rv2) {
    int i = blockIdx.x * blockDim.x + threadIdx.x;
    if (i < 512) {
        float s = g1[i] * rsqrtf(rv1[i] + EPSF);
        g_bn1_s[i] = s;
        g_bn1_t[i] = (b1[i] - rm1[i]) * s + be1[i];
    }
    if (i < 256) {
        float s = g2[i] * rsqrtf(rv2[i] + EPSF);
        g_bn2_s[i] = s;
        g_bn2_t[i] = (b2[i] - rm2[i]) * s + be2[i];
    }
}

__global__ void prep_w1_kernel(const float* __restrict__ W1) {
    int idx = blockIdx.x * blockDim.x + threadIdx.x;
    if (idx >= 512 * KC) return;
    int n = idx / KC;
    int k = idx % KC;
    int orig = (k < 640) ? (k + 128) : (k + 768);
    g_W1T[idx] = __float2half_rn(W1[(size_t)orig * 512 + n]);
}

__global__ void prep_w2_kernel(const float* __restrict__ W2) {
    int idx = blockIdx.x * blockDim.x + threadIdx.x;
    if (idx >= 256 * 512) return;
    int n = idx / 512;
    int k = idx % 512;
    g_W2T[idx] = __float2half_rn(W2[(size_t)k * 256 + n]);
}

__global__ void prep_sq_kernel(const float* __restrict__ W, __half* __restrict__ T) {
    int idx = blockIdx.x * blockDim.x + threadIdx.x;
    if (idx >= 128 * 128) return;
    int n = idx >> 7;
    int k = idx & 127;
    T[idx] = __float2half_rn(W[k * 128 + n]);
}

__global__ void split_xd_kernel(const float* __restrict__ x) {
    int idx = blockIdx.x * blockDim.x + threadIdx.x;
    if (idx >= Bsz * EDIM) return;
    g_xd[idx] = __float2half_rn(x[idx]);
}

// ======== mma.sync fp16 GEMM: C = epi(A@B^T) ================================
// CTA tile 128x128, 8 warps (4m x 2n), BK=64, 3-stage cp.async, 2 CTAs/SM,
// XOR-swizzled smem (128B rows), pass-outer MMA ordering,
// ONE __syncthreads per K-chunk.
// MODE: 1 = fp32 + shift (mm);
//       3 = fp16 out + scale/shift + relu (h1);
//       5 = scale/shift + relu + fused W3 dot -> per-CTA partials (h2+final);
//       6 = plain fp16 out (xw)
// A_FROM_C: A rows are xs fields 2..5 stored inside c (row r -> c[r>>2, ((r&3)+1)*128 ...])
#define MMG_ARR 16384                         // 128 rows x 128 B per operand tile
#define MMG_SMEM (3 * 2 * MMG_ARR)            // 98304 B

template <int MODE, bool A_FROM_C>
__global__ void __launch_bounds__(256, 2)
mma_gemm(const __half* __restrict__ Ah,
         const __half* __restrict__ Bh,
         int K,
         const float* __restrict__ scale, const float* __restrict__ shift,
         float* __restrict__ Cf, __half* __restrict__ Ch, int ldC,
         const float* __restrict__ w3) {
    constexpr int STAGE = 2 * MMG_ARR;
    extern __shared__ char smem[];
    const uint32_t sbase = smem_u32(smem);
    const int tid    = threadIdx.x;
    const int wid    = tid >> 5;
    const int lane   = tid & 31;
    const int warp_m = wid & 3;
    const int warp_n = wid >> 2;
    const int m0     = blockIdx.y * 128;
    const int bcol   = blockIdx.x * 128;
    const int nch    = K >> 6;               // BK = 64

    float acc[2][8][4];
    #pragma unroll
    for (int a = 0; a < 2; a++)
        #pragma unroll
        for (int b = 0; b < 8; b++)
            #pragma unroll
            for (int c = 0; c < 4; c++) acc[a][b][c] = 0.0f;

    auto load_stage = [&](int st, int k0) {
        const uint32_t sdst = sbase + st * STAGE;
        #pragma unroll
        for (int i = 0; i < 8; i++) {
            int c   = tid + i * 256;
            int a   = c >> 10;               // 0 = A, 1 = B (uniform per i)
            int idx = c & 1023;
            int r   = idx >> 3;
            int cc  = idx & 7;
            const __half* g;
            if (a == 0) {
                if (A_FROM_C) {
                    int rr = m0 + r;         // global row = b*4 + jf
                    g = Ah + (size_t)(rr >> 2) * KC + ((rr & 3) + 1) * 128 + k0 + cc * 8;
                } else {
                    g = Ah + (size_t)(m0 + r) * K + k0 + cc * 8;
                }
            } else {
                g = Bh + (size_t)(bcol + r) * K + k0 + cc * 8;
            }
            cp_async16(sdst + a * MMG_ARR + swz(r, cc), g);
        }
        CP_COMMIT();
    };

    load_stage(0, 0);
    if (nch > 1) load_stage(1, 64);

    const int lrow = lane & 15;
    const int lcol = lane >> 4;
    int st = 0;

    for (int ch = 0; ch < nch; ch++) {
        if (ch + 1 < nch) { CP_WAIT1(); } else { CP_WAIT0(); }
        __syncthreads();
        if (ch + 2 < nch) {
            int st2 = st + 2; if (st2 >= 3) st2 -= 3;
            load_stage(st2, (ch + 2) << 6);
        }

        const uint32_t sa = sbase + st * STAGE;
        const uint32_t sb = sa + MMG_ARR;

        #pragma unroll
        for (int kk = 0; kk < 4; kk++) {
            uint32_t ah[2][4];
            #pragma unroll
            for (int mt = 0; mt < 2; mt++) {
                int row = warp_m * 32 + mt * 16 + lrow;
                ldsm_x4(ah[mt], sa + swz(row, kk * 2 + lcol));
            }
            #pragma unroll
            for (int q = 0; q < 4; q++) {
                uint32_t bh[4];
                int row = warp_n * 64 + q * 16 + lrow;
                ldsm_x4(bh, sb + swz(row, kk * 2 + lcol));
                #pragma unroll
                for (int mt = 0; mt < 2; mt++)
                    #pragma unroll
                    for (int sl = 0; sl < 2; sl++)
                        MMA_F16(acc[mt][q * 2 + sl], ah[mt], bh[sl], bh[sl + 2]);
            }
        }
        st++; if (st >= 3) st = 0;
    }

    // ---- fused epilogue ----
    float part[2][2] = {{0.f, 0.f}, {0.f, 0.f}};
    #pragma unroll
    for (int mt = 0; mt < 2; mt++) {
        const int rbase = m0 + warp_m * 32 + mt * 16 + (lane >> 2);
        #pragma unroll
        for (int nt = 0; nt < 8; nt++) {
            const int col = bcol + warp_n * 64 + nt * 8 + (lane & 3) * 2;
            float s0 = 1.0f, s1 = 1.0f, t0 = 0.0f, t1 = 0.0f;
            if (MODE == 3 || MODE == 5) { s0 = scale[col]; s1 = scale[col + 1]; }
            if (MODE == 1 || MODE == 3 || MODE == 5) { t0 = shift[col]; t1 = shift[col + 1]; }
            #pragma unroll
            for (int h = 0; h < 2; h++) {
                const size_t row = (size_t)(rbase + h * 8);
                float v0 = acc[mt][nt][h * 2 + 0];
                float v1 = acc[mt][nt][h * 2 + 1];
                if (MODE == 3 || MODE == 5) {
                    v0 = fmaxf(v0 * s0 + t0, 0.0f);
                    v1 = fmaxf(v1 * s1 + t1, 0.0f);
                } else if (MODE == 1) {
                    v0 += t0; v1 += t1;
                }
                if (MODE == 3 || MODE == 6) {
                    *(__half2*)&Ch[row * ldC + col] =
                        __halves2half2(__float2half_rn(v0), __float2half_rn(v1));
                } else if (MODE == 5) {
                    part[mt][h] += v0 * w3[col] + v1 * w3[col + 1];
                } else {
                    float2 fv; fv.x = v0; fv.y = v1;
                    *(float2*)&Cf[row * ldC + col] = fv;
                }
            }
        }
    }
    if (MODE == 5) {
        #pragma unroll
        for (int mt = 0; mt < 2; mt++) {
            #pragma unroll
            for (int h = 0; h < 2; h++) {
                float p = part[mt][h];
                p += __shfl_xor_sync(0xffffffffu, p, 1);
                p += __shfl_xor_sync(0xffffffffu, p, 2);
                if ((lane & 3) == 0) {
                    const int row = m0 + warp_m * 32 + mt * 16 + (lane >> 2) + h * 8;
                    Cf[(size_t)row * 4 + blockIdx.x * 2 + warp_n] = p;
                }
            }
        }
    }
}

// ---------------- per-row feature construction (exact R11 form) -------------
__device__ __forceinline__ float block_sum_128(float v, float* sred) {
    int lane = threadIdx.x & 31, wid = threadIdx.x >> 5;
    #pragma unroll
    for (int o = 16; o; o >>= 1) v += __shfl_xor_sync(0xffffffffu, v, o);
    if (lane == 0) sred[wid] = v;
    __syncthreads();
    float s = sred[0] + sred[1] + sred[2] + sred[3];
    __syncthreads();
    return s;
}

__global__ void features_kernel(const int* __restrict__ item_id,
                                const int* __restrict__ likes,
                                const int* __restrict__ views,
                                const int* __restrict__ item_seq,
                                const float* __restrict__ item_emb,
                                const float* __restrict__ cate_emb,
                                const float* __restrict__ ln_g,
                                const float* __restrict__ ln_b,
                                const float* __restrict__ se_W1,
                                const float* __restrict__ se_b1,
                                const float* __restrict__ se_W2,
                                const float* __restrict__ se_b2) {
    __shared__ float sred[4];
    __shared__ float sh_hist[4][EDIM];
    __shared__ int   scnt[4];
    __shared__ int   s_idx[HIST];
    const int b    = blockIdx.x;
    const int tid  = threadIdx.x;
    const int wid  = tid >> 5;
    const int lane = tid & 31;

    if (tid < HIST) s_idx[tid] = item_seq[(size_t)b * HIST + tid];
    __syncthreads();

    {
        float4 hs = make_float4(0.f, 0.f, 0.f, 0.f);
        int c = 0;
        for (int t = wid; t < HIST; t += 4) {
            int s = s_idx[t];
            if (s != 0) {
                float4 v = ((const float4*)(item_emb + (size_t)s * EDIM))[lane];
                hs.x += v.x; hs.y += v.y; hs.z += v.z; hs.w += v.w;
                c++;
            }
        }
        ((float4*)sh_hist[wid])[lane] = hs;
        if (lane == 0) scnt[wid] = c;
    }
    __syncthreads();

    const int e = tid;
    float hsum = sh_hist[0][e] + sh_hist[1][e] + sh_hist[2][e] + sh_hist[3][e];
    int   cnt  = scnt[0] + scnt[1] + scnt[2] + scnt[3];
    float hist = hsum / (float)(cnt > 1 ? cnt : 1);
    __syncthreads();

    float mmv = g_mm_pre[(size_t)b * EDIM + e];
    float mu  = block_sum_128(mmv, sred) * (1.0f / 128.0f);
    float d   = mmv - mu;
    float var = block_sum_128(d * d, sred) * (1.0f / 128.0f);
    float mm  = fmaxf(d * rsqrtf(var + EPSF) * ln_g[e] + ln_b[e], 0.0f);

    int   id   = item_id[b];
    float item = (id == 0) ? 0.0f : item_emb[(size_t)id * EDIM + e];
    float like = cate_emb[(size_t)likes[b] * EDIM + e];
    float view = cate_emb[(size_t)views[b] * EDIM + e];

    float x[6] = {0.0f, like, view, item, mm, hist};

    float z[6];
    z[0] = 0.0f;
    #pragma unroll
    for (int f = 1; f < 6; f++) z[f] = block_sum_128(x[f], sred) * (1.0f / 128.0f);

    float w[6];
    {
        float h[3];
        #pragma unroll
        for (int j = 0; j < 3; j++) {
            float s = se_b1[j];
            #pragma unroll
            for (int f = 0; f < 6; f++) s += z[f] * se_W1[f * 3 + j];
            h[j] = fmaxf(s, 0.0f);
        }
        #pragma unroll
        for (int f = 0; f < 6; f++) {
            float s = se_b2[f];
            #pragma unroll
            for (int j = 0; j < 3; j++) s += h[j] * se_W2[j * 6 + f];
            w[f] = 1.0f / (1.0f + expf(-s));
        }
    }

    #pragma unroll
    for (int f = 1; f < 6; f++) {
        float xv = x[f] * w[f];
        g_c[(size_t)b * KC + (f - 1) * EDIM + e] = __float2half_rn(xv);
    }
}

// ---------------- bilinear pair products: half2-vectorized ------------------
// grid Bsz/4, block 256: thread handles (b = blk*4 + tid/64, e-pair = tid%64).
__global__ void pairs_kernel() {
    const int tid = threadIdx.x;
    const int b   = blockIdx.x * 4 + (tid >> 6);
    const int e2  = tid & 63;                 // half2 index: elems 2*e2, 2*e2+1
    const size_t cb0 = (size_t)b * KC + e2 * 2;
    float2 xs0 = __half22float2(*(const __half2*)&g_c[cb0]);
    float2 xs1 = __half22float2(*(const __half2*)&g_c[cb0 + EDIM]);
    float2 xs2 = __half22float2(*(const __half2*)&g_c[cb0 + 2 * EDIM]);
    float2 xs3 = __half22float2(*(const __half2*)&g_c[cb0 + 3 * EDIM]);
    const size_t x4 = (size_t)b * 4 * EDIM + e2 * 2;
    float2 xw0 = __half22float2(*(const __half2*)&g_xw[x4]);
    float2 xw1 = __half22float2(*(const __half2*)&g_xw[x4 + EDIM]);
    float2 xw2 = __half22float2(*(const __half2*)&g_xw[x4 + 2 * EDIM]);
    float2 xw3 = __half22float2(*(const __half2*)&g_xw[x4 + 3 * EDIM]);

    float2 p[10];
    p[0].x = xs0.x * xw0.x; p[0].y = xs0.y * xw0.y;
    p[1].x = xs0.x * xw1.x; p[1].y = xs0.y * xw1.y;
    p[2].x = xs0.x * xw2.x; p[2].y = xs0.y * xw2.y;
    p[3].x = xs0.x * xw3.x; p[3].y = xs0.y * xw3.y;
    p[4].x = xs1.x * xw1.x; p[4].y = xs1.y * xw1.y;
    p[5].x = xs1.x * xw2.x; p[5].y = xs1.y * xw2.y;
    p[6].x = xs1.x * xw3.x; p[6].y = xs1.y * xw3.y;
    p[7].x = xs2.x * xw2.x; p[7].y = xs2.y * xw2.y;
    p[8].x = xs2.x * xw3.x; p[8].y = xs2.y * xw3.y;
    p[9].x = xs3.x * xw3.x; p[9].y = xs3.y * xw3.y;

    const size_t cb = cb0 + 640;
    #pragma unroll
    for (int pr = 0; pr < 10; pr++)
        *(__half2*)&g_c[cb + pr * EDIM] =
            __halves2half2(__float2half_rn(p[pr].x), __float2half_rn(p[pr].y));
}

// ---------------- final: sum partials + bias + sigmoid ---------------------
__global__ void final_sig_kernel(const float* __restrict__ b3, float* __restrict__ out) {
    int b = blockIdx.x * blockDim.x + threadIdx.x;
    if (b >= Bsz) return;
    float4 pp = *(const float4*)&g_part[b * 4];
    float l = pp.x + pp.y + pp.z + pp.w + b3[0];
    out[b] = 1.0f / (1.0f + expf(-l));
}

// ---------------- launch ----------------------------------------------------
extern "C" void kernel_launch(void* const* d_in, const int* in_sizes, int n_in,
                              void* d_out, int out_size) {
    const int*   item_id   = (const int*)  d_in[0];
    const float* x_d128    = (const float*)d_in[1];
    const int*   likes     = (const int*)  d_in[2];
    const int*   views     = (const int*)  d_in[3];
    const int*   item_seq  = (const int*)  d_in[4];
    const float* item_emb  = (const float*)d_in[5];
    const float* cate_emb  = (const float*)d_in[6];
    const float* mm_W      = (const float*)d_in[7];
    const float* mm_b      = (const float*)d_in[8];
    const float* ln_g      = (const float*)d_in[9];
    const float* ln_b      = (const float*)d_in[10];
    const float* se_W1     = (const float*)d_in[11];
    const float* se_b1     = (const float*)d_in[12];
    const float* se_W2     = (const float*)d_in[13];
    const float* se_b2     = (const float*)d_in[14];
    const float* bi_W      = (const float*)d_in[15];
    const float* mlp_W1    = (const float*)d_in[16];
    const float* mlp_b1    = (const float*)d_in[17];
    const float* bn1_g     = (const float*)d_in[18];
    const float* bn1_b     = (const float*)d_in[19];
    const float* bn1_rm    = (const float*)d_in[20];
    const float* bn1_rv    = (const float*)d_in[21];
    const float* mlp_W2    = (const float*)d_in[22];
    const float* mlp_b2    = (const float*)d_in[23];
    const float* bn2_g     = (const float*)d_in[24];
    const float* bn2_b     = (const float*)d_in[25];
    const float* bn2_rm    = (const float*)d_in[26];
    const float* bn2_rv    = (const float*)d_in[27];
    const float* mlp_W3    = (const float*)d_in[28];
    const float* mlp_b3    = (const float*)d_in[29];
    float*       out       = (float*)d_out;

    float *p_mm_pre, *p_part;
    float *p_bn1_s, *p_bn1_t, *p_bn2_s, *p_bn2_t;
    __half *p_c, *p_h1, *p_xw, *p_W1T, *p_W2T, *p_xd, *p_mmWT, *p_biWT;
    cudaGetSymbolAddress((void**)&p_mm_pre, g_mm_pre);
    cudaGetSymbolAddress((void**)&p_xw,     g_xw);
    cudaGetSymbolAddress((void**)&p_part,   g_part);
    cudaGetSymbolAddress((void**)&p_c,      g_c);
    cudaGetSymbolAddress((void**)&p_h1,     g_h1);
    cudaGetSymbolAddress((void**)&p_W1T,    g_W1T);
    cudaGetSymbolAddress((void**)&p_W2T,    g_W2T);
    cudaGetSymbolAddress((void**)&p_xd,     g_xd);
    cudaGetSymbolAddress((void**)&p_mmWT,   g_mmWT);
    cudaGetSymbolAddress((void**)&p_biWT,   g_biWT);
    cudaGetSymbolAddress((void**)&p_bn1_s,  g_bn1_s);
    cudaGetSymbolAddress((void**)&p_bn1_t,  g_bn1_t);
    cudaGetSymbolAddress((void**)&p_bn2_s,  g_bn2_s);
    cudaGetSymbolAddress((void**)&p_bn2_t,  g_bn2_t);

    cudaFuncSetAttribute((const void*)mma_gemm<1, false>,
                         cudaFuncAttributeMaxDynamicSharedMemorySize, MMG_SMEM);
    cudaFuncSetAttribute((const void*)mma_gemm<6, true >,
                         cudaFuncAttributeMaxDynamicSharedMemorySize, MMG_SMEM);
    cudaFuncSetAttribute((const void*)mma_gemm<3, false>,
                         cudaFuncAttributeMaxDynamicSharedMemorySize, MMG_SMEM);
    cudaFuncSetAttribute((const void*)mma_gemm<5, false>,
                         cudaFuncAttributeMaxDynamicSharedMemorySize, MMG_SMEM);

    // ---- fork: preps on side stream ----
    cudaEventRecord(g_ss.fork, 0);
    cudaStreamWaitEvent(g_ss.s, g_ss.fork, 0);
    prep_sq_kernel<<<(128 * 128 + 255) / 256, 256, 0, g_ss.s>>>(mm_W, p_mmWT);
    cudaEventRecord(g_ss.join2, g_ss.s);          // mm GEMM needs mmWT
    prep_bn_kernel<<<1, 512, 0, g_ss.s>>>(mlp_b1, bn1_g, bn1_b, bn1_rm, bn1_rv,
                                          mlp_b2, bn2_g, bn2_b, bn2_rm, bn2_rv);
    prep_w1_kernel<<<(512 * KC + 255) / 256, 256, 0, g_ss.s>>>(mlp_W1);
    prep_w2_kernel<<<(256 * 512 + 255) / 256, 256, 0, g_ss.s>>>(mlp_W2);
    prep_sq_kernel<<<(128 * 128 + 255) / 256, 256, 0, g_ss.s>>>(bi_W, p_biWT);
    cudaEventRecord(g_ss.join, g_ss.s);

    // ---- main chain ----
    split_xd_kernel<<<(Bsz * EDIM + 255) / 256, 256>>>(x_d128);
    cudaStreamWaitEvent(0, g_ss.join2, 0);

    // mm_pre = item_emb_d128 @ mm_W + mm_b   (single-pass fp16; MODE 1)
    mma_gemm<1, false><<<dim3(1, Bsz / 128), 256, MMG_SMEM>>>(
        p_xd, p_mmWT, 128,
        nullptr, mm_b, p_mm_pre, nullptr, 128, nullptr);

    // per-row features -> c[:,0:640]
    features_kernel<<<Bsz, 128>>>(item_id, likes, views, item_seq,
                                  item_emb, cate_emb, ln_g, ln_b,
                                  se_W1, se_b1, se_W2, se_b2);

    cudaStreamWaitEvent(0, g_ss.join, 0);

    // xw = xs(fields 2..5, from c) @ bi_W -> fp16  (MODE 6, A_FROM_C)
    mma_gemm<6, true><<<dim3(1, (Bsz * 4) / 128), 256, MMG_SMEM>>>(
        p_c, p_biWT, 128,
        nullptr, nullptr, nullptr, p_xw, 128, nullptr);

    // pair products -> c[:, 640:1920]  (half2-vectorized)
    pairs_kernel<<<Bsz / 4, 256>>>();

    // h1 = relu(bn1(c @ W1c^T + b1))   (MODE 3, K=1920)
    mma_gemm<3, false><<<dim3(512 / 128, Bsz / 128), 256, MMG_SMEM>>>(
        p_c, p_W1T, KC,
        p_bn1_s, p_bn1_t, nullptr, p_h1, 512, nullptr);

    // h2+final: relu(bn2(h1 @ W2^T + b2)) . W3 -> partials (MODE 5)
    mma_gemm<5, false><<<dim3(256 / 128, Bsz / 128), 256, MMG_SMEM>>>(
        p_h1, p_W2T, 512,
        p_bn2_s, p_bn2_t, p_part, nullptr, 4, mlp_W3);

    // logits -> sigmoid
    final_sig_kernel<<<(Bsz + 255) / 256, 256>>>(mlp_b3, out);
}

// round 17
// speedup vs baseline: 1.2359x; 1.0504x over previous
#include <cuda_runtime.h>
#include <cuda_fp16.h>
#include <math.h>
#include <stdint.h>

#define Bsz  16384
#define EDIM 128
#define HIST 50
#define KC   1920   // compact K for MLP1 (zero columns of c removed)
#define EPSF 1e-5f

// ---------------- scratch (device globals; no allocation allowed) ----------
__device__ float g_mm_pre[Bsz * EDIM];                       //  8.4 MB
__device__ __half g_xw[Bsz * 4 * EDIM];                      // 16.8 MB (fields 2..5 @ bi_W)
__device__ __half g_c[(size_t)Bsz * KC];                     // 63 MB (single fp16)
__device__ __half g_h1[Bsz * 512];                           // 16.8 MB
__device__ float g_part[Bsz * 4];                            // 256 KB logit partials
__device__ __half g_W1T[512 * KC];                           //  2 MB (N-major [512][1920])
__device__ __half g_W2T[256 * 512];
__device__ __half g_mmWT[128 * 128];
__device__ __half g_biWT[128 * 128];
__device__ float g_bn1_s[512], g_bn1_t[512];
__device__ float g_bn2_s[256], g_bn2_t[256];

// ---------------- side stream for prep overlap (created at load time) ------
struct SideStream {
    cudaStream_t s;
    cudaEvent_t  fork, join, join2;
    SideStream() {
        cudaStreamCreateWithFlags(&s, cudaStreamNonBlocking);
        cudaEventCreateWithFlags(&fork,  cudaEventDisableTiming);
        cudaEventCreateWithFlags(&join,  cudaEventDisableTiming);
        cudaEventCreateWithFlags(&join2, cudaEventDisableTiming);
    }
};
static SideStream g_ss;

// ================= PTX helpers (non-arch-specific only) =====================
__device__ __forceinline__ uint32_t smem_u32(const void* p) {
    uint32_t a;
    asm("{ .reg .u64 t; cvta.to.shared.u64 t, %1; cvt.u32.u64 %0, t; }"
        : "=r"(a) : "l"(p));
    return a;
}
__device__ __forceinline__ void cp_async16(uint32_t dst, const void* src) {
    asm volatile("cp.async.cg.shared.global [%0], [%1], 16;" :: "r"(dst), "l"(src));
}
#define CP_COMMIT() asm volatile("cp.async.commit_group;" ::: "memory")
#define CP_WAIT0()  asm volatile("cp.async.wait_group 0;" ::: "memory")
#define CP_WAIT1()  asm volatile("cp.async.wait_group 1;" ::: "memory")

__device__ __forceinline__ void ldsm_x4(uint32_t* r, uint32_t addr) {
    asm volatile("ldmatrix.sync.aligned.m8n8.x4.shared.b16 {%0,%1,%2,%3}, [%4];"
                 : "=r"(r[0]), "=r"(r[1]), "=r"(r[2]), "=r"(r[3]) : "r"(addr));
}
#define MMA_F16(c, a, b0v, b1v) \
    asm volatile("mma.sync.aligned.m16n8k16.row.col.f32.f16.f16.f32 " \
        "{%0,%1,%2,%3}, {%4,%5,%6,%7}, {%8,%9}, {%0,%1,%2,%3};" \
        : "+f"((c)[0]), "+f"((c)[1]), "+f"((c)[2]), "+f"((c)[3]) \
        : "r"((a)[0]), "r"((a)[1]), "r"((a)[2]), "r"((a)[3]), "r"(b0v), "r"(b1v))

// XOR-swizzled smem addressing: 128 rows x 128 B (64 fp16). unit = 16B column (0..7).
__device__ __forceinline__ uint32_t swz(int row, int unit) {
    return (uint32_t)(row * 128 + ((unit ^ (row & 7)) << 4));
}

// ---------------- prep kernels ----------------------------------------------
__global__ void prep_bn_kernel(const float* __restrict__ b1, const float* __restrict__ g1,
                               const float* __restrict__ be1, const float* __restrict__ rm1,
                               const float* __restrict__ rv1,
                               const float* __restrict__ b2, const float* __restrict__ g2,
                               const float* __restrict__ be2, const float* __restrict__ rm2,
                               const float* __restrict__ rv2) {
    int i = blockIdx.x * blockDim.x + threadIdx.x;
    if (i < 512) {
        float s = g1[i] * rsqrtf(rv1[i] + EPSF);
        g_bn1_s[i] = s;
        g_bn1_t[i] = (b1[i] - rm1[i]) * s + be1[i];
    }
    if (i < 256) {
        float s = g2[i] * rsqrtf(rv2[i] + EPSF);
        g_bn2_s[i] = s;
        g_bn2_t[i] = (b2[i] - rm2[i]) * s + be2[i];
    }
}

__global__ void prep_w1_kernel(const float* __restrict__ W1) {
    int idx = blockIdx.x * blockDim.x + threadIdx.x;
    if (idx >= 512 * KC) return;
    int n = idx / KC;
    int k = idx % KC;
    int orig = (k < 640) ? (k + 128) : (k + 768);
    g_W1T[idx] = __float2half_rn(W1[(size_t)orig * 512 + n]);
}

__global__ void prep_w2_kernel(const float* __restrict__ W2) {
    int idx = blockIdx.x * blockDim.x + threadIdx.x;
    if (idx >= 256 * 512) return;
    int n = idx / 512;
    int k = idx % 512;
    g_W2T[idx] = __float2half_rn(W2[(size_t)k * 256 + n]);
}

__global__ void prep_sq_kernel(const float* __restrict__ W, __half* __restrict__ T) {
    int idx = blockIdx.x * blockDim.x + threadIdx.x;
    if (idx >= 128 * 128) return;
    int n = idx >> 7;
    int k = idx & 127;
    T[idx] = __float2half_rn(W[k * 128 + n]);
}

// ======== mma.sync fp16 GEMM: C = epi(A@B^T) ================================
// CTA tile 128x128, 8 warps (4m x 2n), BK=64, 3-stage cp.async, 2 CTAs/SM,
// XOR-swizzled smem (128B rows), pass-outer MMA ordering,
// ONE __syncthreads per K-chunk.
// MODE: 1 = fp32 + shift (mm);
//       3 = fp16 out + scale/shift + relu (h1);
//       5 = scale/shift + relu + fused W3 dot -> per-CTA partials (h2+final);
//       6 = plain fp16 out (xw)
// A_FROM_C: A rows are xs fields 2..5 stored inside c (row r -> c[r>>2, ((r&3)+1)*128 ...])
// A_F32:    A is fp32 in gmem; loaded via LDG + register convert + STS.
#define MMG_ARR 16384                         // 128 rows x 128 B per operand tile
#define MMG_SMEM (3 * 2 * MMG_ARR)            // 98304 B

template <int MODE, bool A_FROM_C, bool A_F32>
__global__ void __launch_bounds__(256, 2)
mma_gemm(const __half* __restrict__ Ah, const float* __restrict__ Af,
         const __half* __restrict__ Bh,
         int K,
         const float* __restrict__ scale, const float* __restrict__ shift,
         float* __restrict__ Cf, __half* __restrict__ Ch, int ldC,
         const float* __restrict__ w3) {
    constexpr int STAGE = 2 * MMG_ARR;
    extern __shared__ char smem[];
    const uint32_t sbase = smem_u32(smem);
    const int tid    = threadIdx.x;
    const int wid    = tid >> 5;
    const int lane   = tid & 31;
    const int warp_m = wid & 3;
    const int warp_n = wid >> 2;
    const int m0     = blockIdx.y * 128;
    const int bcol   = blockIdx.x * 128;
    const int nch    = K >> 6;               // BK = 64

    float acc[2][8][4];
    #pragma unroll
    for (int a = 0; a < 2; a++)
        #pragma unroll
        for (int b = 0; b < 8; b++)
            #pragma unroll
            for (int c = 0; c < 4; c++) acc[a][b][c] = 0.0f;

    auto load_stage = [&](int st, int k0) {
        const uint32_t sdst = sbase + st * STAGE;
        #pragma unroll
        for (int i = 0; i < 8; i++) {
            int c   = tid + i * 256;
            int a   = c >> 10;               // 0 = A, 1 = B (uniform per i)
            int idx = c & 1023;
            int r   = idx >> 3;
            int cc  = idx & 7;
            if (a == 0 && A_F32) {
                // fp32 A: two LDG.128 -> 8 halves -> one STS.128
                const float4* gf = (const float4*)(Af + (size_t)(m0 + r) * K + k0 + cc * 8);
                float4 f0 = gf[0], f1 = gf[1];
                __half2 h0 = __halves2half2(__float2half_rn(f0.x), __float2half_rn(f0.y));
                __half2 h1 = __halves2half2(__float2half_rn(f0.z), __float2half_rn(f0.w));
                __half2 h2 = __halves2half2(__float2half_rn(f1.x), __float2half_rn(f1.y));
                __half2 h3 = __halves2half2(__float2half_rn(f1.z), __float2half_rn(f1.w));
                uint4 v;
                v.x = *(uint32_t*)&h0; v.y = *(uint32_t*)&h1;
                v.z = *(uint32_t*)&h2; v.w = *(uint32_t*)&h3;
                *(uint4*)(smem + (sdst - sbase) + swz(r, cc)) = v;
            } else {
                const __half* g;
                if (a == 0) {
                    if (A_FROM_C) {
                        int rr = m0 + r;     // global row = b*4 + jf
                        g = Ah + (size_t)(rr >> 2) * KC + ((rr & 3) + 1) * 128 + k0 + cc * 8;
                    } else {
                        g = Ah + (size_t)(m0 + r) * K + k0 + cc * 8;
                    }
                } else {
                    g = Bh + (size_t)(bcol + r) * K + k0 + cc * 8;
                }
                cp_async16(sdst + a * MMG_ARR + swz(r, cc), g);
            }
        }
        CP_COMMIT();
    };

    load_stage(0, 0);
    if (nch > 1) load_stage(1, 64);

    const int lrow = lane & 15;
    const int lcol = lane >> 4;
    int st = 0;

    for (int ch = 0; ch < nch; ch++) {
        if (ch + 1 < nch) { CP_WAIT1(); } else { CP_WAIT0(); }
        __syncthreads();
        if (ch + 2 < nch) {
            int st2 = st + 2; if (st2 >= 3) st2 -= 3;
            load_stage(st2, (ch + 2) << 6);
        }

        const uint32_t sa = sbase + st * STAGE;
        const uint32_t sb = sa + MMG_ARR;

        #pragma unroll
        for (int kk = 0; kk < 4; kk++) {
            uint32_t ah[2][4];
            #pragma unroll
            for (int mt = 0; mt < 2; mt++) {
                int row = warp_m * 32 + mt * 16 + lrow;
                ldsm_x4(ah[mt], sa + swz(row, kk * 2 + lcol));
            }
            #pragma unroll
            for (int q = 0; q < 4; q++) {
                uint32_t bh[4];
                int row = warp_n * 64 + q * 16 + lrow;
                ldsm_x4(bh, sb + swz(row, kk * 2 + lcol));
                #pragma unroll
                for (int mt = 0; mt < 2; mt++)
                    #pragma unroll
                    for (int sl = 0; sl < 2; sl++)
                        MMA_F16(acc[mt][q * 2 + sl], ah[mt], bh[sl], bh[sl + 2]);
            }
        }
        st++; if (st >= 3) st = 0;

        if (A_F32) __syncthreads();   // protect sync-STS stage reuse (small K only)
    }

    // ---- fused epilogue ----
    float part[2][2] = {{0.f, 0.f}, {0.f, 0.f}};
    #pragma unroll
    for (int mt = 0; mt < 2; mt++) {
        const int rbase = m0 + warp_m * 32 + mt * 16 + (lane >> 2);
        #pragma unroll
        for (int nt = 0; nt < 8; nt++) {
            const int col = bcol + warp_n * 64 + nt * 8 + (lane & 3) * 2;
            float s0 = 1.0f, s1 = 1.0f, t0 = 0.0f, t1 = 0.0f;
            if (MODE == 3 || MODE == 5) { s0 = scale[col]; s1 = scale[col + 1]; }
            if (MODE == 1 || MODE == 3 || MODE == 5) { t0 = shift[col]; t1 = shift[col + 1]; }
            #pragma unroll
            for (int h = 0; h < 2; h++) {
                const size_t row = (size_t)(rbase + h * 8);
                float v0 = acc[mt][nt][h * 2 + 0];
                float v1 = acc[mt][nt][h * 2 + 1];
                if (MODE == 3 || MODE == 5) {
                    v0 = fmaxf(v0 * s0 + t0, 0.0f);
                    v1 = fmaxf(v1 * s1 + t1, 0.0f);
                } else if (MODE == 1) {
                    v0 += t0; v1 += t1;
                }
                if (MODE == 3 || MODE == 6) {
                    *(__half2*)&Ch[row * ldC + col] =
                        __halves2half2(__float2half_rn(v0), __float2half_rn(v1));
                } else if (MODE == 5) {
                    part[mt][h] += v0 * w3[col] + v1 * w3[col + 1];
                } else {
                    float2 fv; fv.x = v0; fv.y = v1;
                    *(float2*)&Cf[row * ldC + col] = fv;
                }
            }
        }
    }
    if (MODE == 5) {
        #pragma unroll
        for (int mt = 0; mt < 2; mt++) {
            #pragma unroll
            for (int h = 0; h < 2; h++) {
                float p = part[mt][h];
                p += __shfl_xor_sync(0xffffffffu, p, 1);
                p += __shfl_xor_sync(0xffffffffu, p, 2);
                if ((lane & 3) == 0) {
                    const int row = m0 + warp_m * 32 + mt * 16 + (lane >> 2) + h * 8;
                    Cf[(size_t)row * 4 + blockIdx.x * 2 + warp_n] = p;
                }
            }
        }
    }
}

// ---------------- per-row feature construction (exact R11 form) -------------
__device__ __forceinline__ float block_sum_128(float v, float* sred) {
    int lane = threadIdx.x & 31, wid = threadIdx.x >> 5;
    #pragma unroll
    for (int o = 16; o; o >>= 1) v += __shfl_xor_sync(0xffffffffu, v, o);
    if (lane == 0) sred[wid] = v;
    __syncthreads();
    float s = sred[0] + sred[1] + sred[2] + sred[3];
    __syncthreads();
    return s;
}

__global__ void features_kernel(const int* __restrict__ item_id,
                                const int* __restrict__ likes,
                                const int* __restrict__ views,
                                const int* __restrict__ item_seq,
                                const float* __restrict__ item_emb,
                                const float* __restrict__ cate_emb,
                                const float* __restrict__ ln_g,
                                const float* __restrict__ ln_b,
                                const float* __restrict__ se_W1,
                                const float* __restrict__ se_b1,
                                const float* __restrict__ se_W2,
                                const float* __restrict__ se_b2) {
    __shared__ float sred[4];
    __shared__ float sh_hist[4][EDIM];
    __shared__ int   scnt[4];
    __shared__ int   s_idx[HIST];
    const int b    = blockIdx.x;
    const int tid  = threadIdx.x;
    const int wid  = tid >> 5;
    const int lane = tid & 31;

    if (tid < HIST) s_idx[tid] = item_seq[(size_t)b * HIST + tid];
    __syncthreads();

    {
        float4 hs = make_float4(0.f, 0.f, 0.f, 0.f);
        int c = 0;
        for (int t = wid; t < HIST; t += 4) {
            int s = s_idx[t];
            if (s != 0) {
                float4 v = ((const float4*)(item_emb + (size_t)s * EDIM))[lane];
                hs.x += v.x; hs.y += v.y; hs.z += v.z; hs.w += v.w;
                c++;
            }
        }
        ((float4*)sh_hist[wid])[lane] = hs;
        if (lane == 0) scnt[wid] = c;
    }
    __syncthreads();

    const int e = tid;
    float hsum = sh_hist[0][e] + sh_hist[1][e] + sh_hist[2][e] + sh_hist[3][e];
    int   cnt  = scnt[0] + scnt[1] + scnt[2] + scnt[3];
    float hist = hsum / (float)(cnt > 1 ? cnt : 1);
    __syncthreads();

    float mmv = g_mm_pre[(size_t)b * EDIM + e];
    float mu  = block_sum_128(mmv, sred) * (1.0f / 128.0f);
    float d   = mmv - mu;
    float var = block_sum_128(d * d, sred) * (1.0f / 128.0f);
    float mm  = fmaxf(d * rsqrtf(var + EPSF) * ln_g[e] + ln_b[e], 0.0f);

    int   id   = item_id[b];
    float item = (id == 0) ? 0.0f : item_emb[(size_t)id * EDIM + e];
    float like = cate_emb[(size_t)likes[b] * EDIM + e];
    float view = cate_emb[(size_t)views[b] * EDIM + e];

    float x[6] = {0.0f, like, view, item, mm, hist};

    float z[6];
    z[0] = 0.0f;
    #pragma unroll
    for (int f = 1; f < 6; f++) z[f] = block_sum_128(x[f], sred) * (1.0f / 128.0f);

    float w[6];
    {
        float h[3];
        #pragma unroll
        for (int j = 0; j < 3; j++) {
            float s = se_b1[j];
            #pragma unroll
            for (int f = 0; f < 6; f++) s += z[f] * se_W1[f * 3 + j];
            h[j] = fmaxf(s, 0.0f);
        }
        #pragma unroll
        for (int f = 0; f < 6; f++) {
            float s = se_b2[f];
            #pragma unroll
            for (int j = 0; j < 3; j++) s += h[j] * se_W2[j * 6 + f];
            w[f] = 1.0f / (1.0f + expf(-s));
        }
    }

    #pragma unroll
    for (int f = 1; f < 6; f++) {
        float xv = x[f] * w[f];
        g_c[(size_t)b * KC + (f - 1) * EDIM + e] = __float2half_rn(xv);
    }
}

// ---------------- bilinear pair products: half2-vectorized ------------------
__global__ void pairs_kernel() {
    const int tid = threadIdx.x;
    const int b   = blockIdx.x * 4 + (tid >> 6);
    const int e2  = tid & 63;
    const size_t cb0 = (size_t)b * KC + e2 * 2;
    float2 xs0 = __half22float2(*(const __half2*)&g_c[cb0]);
    float2 xs1 = __half22float2(*(const __half2*)&g_c[cb0 + EDIM]);
    float2 xs2 = __half22float2(*(const __half2*)&g_c[cb0 + 2 * EDIM]);
    float2 xs3 = __half22float2(*(const __half2*)&g_c[cb0 + 3 * EDIM]);
    const size_t x4 = (size_t)b * 4 * EDIM + e2 * 2;
    float2 xw0 = __half22float2(*(const __half2*)&g_xw[x4]);
    float2 xw1 = __half22float2(*(const __half2*)&g_xw[x4 + EDIM]);
    float2 xw2 = __half22float2(*(const __half2*)&g_xw[x4 + 2 * EDIM]);
    float2 xw3 = __half22float2(*(const __half2*)&g_xw[x4 + 3 * EDIM]);

    float2 p[10];
    p[0].x = xs0.x * xw0.x; p[0].y = xs0.y * xw0.y;
    p[1].x = xs0.x * xw1.x; p[1].y = xs0.y * xw1.y;
    p[2].x = xs0.x * xw2.x; p[2].y = xs0.y * xw2.y;
    p[3].x = xs0.x * xw3.x; p[3].y = xs0.y * xw3.y;
    p[4].x = xs1.x * xw1.x; p[4].y = xs1.y * xw1.y;
    p[5].x = xs1.x * xw2.x; p[5].y = xs1.y * xw2.y;
    p[6].x = xs1.x * xw3.x; p[6].y = xs1.y * xw3.y;
    p[7].x = xs2.x * xw2.x; p[7].y = xs2.y * xw2.y;
    p[8].x = xs2.x * xw3.x; p[8].y = xs2.y * xw3.y;
    p[9].x = xs3.x * xw3.x; p[9].y = xs3.y * xw3.y;

    const size_t cb = cb0 + 640;
    #pragma unroll
    for (int pr = 0; pr < 10; pr++)
        *(__half2*)&g_c[cb + pr * EDIM] =
            __halves2half2(__float2half_rn(p[pr].x), __float2half_rn(p[pr].y));
}

// ---------------- final: sum partials + bias + sigmoid ---------------------
__global__ void final_sig_kernel(const float* __restrict__ b3, float* __restrict__ out) {
    int b = blockIdx.x * blockDim.x + threadIdx.x;
    if (b >= Bsz) return;
    float4 pp = *(const float4*)&g_part[b * 4];
    float l = pp.x + pp.y + pp.z + pp.w + b3[0];
    out[b] = 1.0f / (1.0f + expf(-l));
}

// ---------------- launch ----------------------------------------------------
extern "C" void kernel_launch(void* const* d_in, const int* in_sizes, int n_in,
                              void* d_out, int out_size) {
    const int*   item_id   = (const int*)  d_in[0];
    const float* x_d128    = (const float*)d_in[1];
    const int*   likes     = (const int*)  d_in[2];
    const int*   views     = (const int*)  d_in[3];
    const int*   item_seq  = (const int*)  d_in[4];
    const float* item_emb  = (const float*)d_in[5];
    const float* cate_emb  = (const float*)d_in[6];
    const float* mm_W      = (const float*)d_in[7];
    const float* mm_b      = (const float*)d_in[8];
    const float* ln_g      = (const float*)d_in[9];
    const float* ln_b      = (const float*)d_in[10];
    const float* se_W1     = (const float*)d_in[11];
    const float* se_b1     = (const float*)d_in[12];
    const float* se_W2     = (const float*)d_in[13];
    const float* se_b2     = (const float*)d_in[14];
    const float* bi_W      = (const float*)d_in[15];
    const float* mlp_W1    = (const float*)d_in[16];
    const float* mlp_b1    = (const float*)d_in[17];
    const float* bn1_g     = (const float*)d_in[18];
    const float* bn1_b     = (const float*)d_in[19];
    const float* bn1_rm    = (const float*)d_in[20];
    const float* bn1_rv    = (const float*)d_in[21];
    const float* mlp_W2    = (const float*)d_in[22];
    const float* mlp_b2    = (const float*)d_in[23];
    const float* bn2_g     = (const float*)d_in[24];
    const float* bn2_b     = (const float*)d_in[25];
    const float* bn2_rm    = (const float*)d_in[26];
    const float* bn2_rv    = (const float*)d_in[27];
    const float* mlp_W3    = (const float*)d_in[28];
    const float* mlp_b3    = (const float*)d_in[29];
    float*       out       = (float*)d_out;

    float *p_mm_pre, *p_part;
    float *p_bn1_s, *p_bn1_t, *p_bn2_s, *p_bn2_t;
    __half *p_c, *p_h1, *p_xw, *p_W1T, *p_W2T, *p_mmWT, *p_biWT;
    cudaGetSymbolAddress((void**)&p_mm_pre, g_mm_pre);
    cudaGetSymbolAddress((void**)&p_xw,     g_xw);
    cudaGetSymbolAddress((void**)&p_part,   g_part);
    cudaGetSymbolAddress((void**)&p_c,      g_c);
    cudaGetSymbolAddress((void**)&p_h1,     g_h1);
    cudaGetSymbolAddress((void**)&p_W1T,    g_W1T);
    cudaGetSymbolAddress((void**)&p_W2T,    g_W2T);
    cudaGetSymbolAddress((void**)&p_mmWT,   g_mmWT);
    cudaGetSymbolAddress((void**)&p_biWT,   g_biWT);
    cudaGetSymbolAddress((void**)&p_bn1_s,  g_bn1_s);
    cudaGetSymbolAddress((void**)&p_bn1_t,  g_bn1_t);
    cudaGetSymbolAddress((void**)&p_bn2_s,  g_bn2_s);
    cudaGetSymbolAddress((void**)&p_bn2_t,  g_bn2_t);

    cudaFuncSetAttribute((const void*)mma_gemm<1, false, true >,
                         cudaFuncAttributeMaxDynamicSharedMemorySize, MMG_SMEM);
    cudaFuncSetAttribute((const void*)mma_gemm<6, true,  false>,
                         cudaFuncAttributeMaxDynamicSharedMemorySize, MMG_SMEM);
    cudaFuncSetAttribute((const void*)mma_gemm<3, false, false>,
                         cudaFuncAttributeMaxDynamicSharedMemorySize, MMG_SMEM);
    cudaFuncSetAttribute((const void*)mma_gemm<5, false, false>,
                         cudaFuncAttributeMaxDynamicSharedMemorySize, MMG_SMEM);

    // ---- fork: preps on side stream ----
    cudaEventRecord(g_ss.fork, 0);
    cudaStreamWaitEvent(g_ss.s, g_ss.fork, 0);
    prep_sq_kernel<<<(128 * 128 + 255) / 256, 256, 0, g_ss.s>>>(mm_W, p_mmWT);
    cudaEventRecord(g_ss.join2, g_ss.s);          // mm GEMM needs mmWT
    prep_bn_kernel<<<1, 512, 0, g_ss.s>>>(mlp_b1, bn1_g, bn1_b, bn1_rm, bn1_rv,
                                          mlp_b2, bn2_g, bn2_b, bn2_rm, bn2_rv);
    prep_w1_kernel<<<(512 * KC + 255) / 256, 256, 0, g_ss.s>>>(mlp_W1);
    prep_w2_kernel<<<(256 * 512 + 255) / 256, 256, 0, g_ss.s>>>(mlp_W2);
    prep_sq_kernel<<<(128 * 128 + 255) / 256, 256, 0, g_ss.s>>>(bi_W, p_biWT);
    cudaEventRecord(g_ss.join, g_ss.s);

    // ---- main chain ----
    cudaStreamWaitEvent(0, g_ss.join2, 0);

    // mm_pre = item_emb_d128 @ mm_W + mm_b   (A fp32 direct-load; MODE 1)
    mma_gemm<1, false, true><<<dim3(1, Bsz / 128), 256, MMG_SMEM>>>(
        nullptr, x_d128, p_mmWT, 128,
        nullptr, mm_b, p_mm_pre, nullptr, 128, nullptr);

    // per-row features -> c[:,0:640]
    features_kernel<<<Bsz, 128>>>(item_id, likes, views, item_seq,
                                  item_emb, cate_emb, ln_g, ln_b,
                                  se_W1, se_b1, se_W2, se_b2);

    cudaStreamWaitEvent(0, g_ss.join, 0);

    // xw = xs(fields 2..5, from c) @ bi_W -> fp16  (MODE 6, A_FROM_C)
    mma_gemm<6, true, false><<<dim3(1, (Bsz * 4) / 128), 256, MMG_SMEM>>>(
        p_c, nullptr, p_biWT, 128,
        nullptr, nullptr, nullptr, p_xw, 128, nullptr);

    // pair products -> c[:, 640:1920]  (half2-vectorized)
    pairs_kernel<<<Bsz / 4, 256>>>();

    // h1 = relu(bn1(c @ W1c^T + b1))   (MODE 3, K=1920)
    mma_gemm<3, false, false><<<dim3(512 / 128, Bsz / 128), 256, MMG_SMEM>>>(
        p_c, nullptr, p_W1T, KC,
        p_bn1_s, p_bn1_t, nullptr, p_h1, 512, nullptr);

    // h2+final: relu(bn2(h1 @ W2^T + b2)) . W3 -> partials (MODE 5)
    mma_gemm<5, false, false><<<dim3(256 / 128, Bsz / 128), 256, MMG_SMEM>>>(
        p_h1, nullptr, p_W2T, 512,
        p_bn2_s, p_bn2_t, p_part, nullptr, 4, mlp_W3);

    // logits -> sigmoid
    final_sig_kernel<<<(Bsz + 255) / 256, 256>>>(mlp_b3, out);
}